// round 15
// baseline (speedup 1.0000x reference)
#include <cuda_runtime.h>
#include <cuda_fp16.h>
#include <math.h>
#include <stdint.h>

#define Bb   2
#define Tt   2048
#define Cc   1024
#define Hh   16
#define DHd  64
#define WINw 256
#define Kk   32
#define DFFf 4096
#define Mrows (Bb*Tt)   // 4096

// ---------------- scratch ----------------
__device__ __half g_h  [Mrows*Cc];
__device__ __half g_qkv[Mrows*3*Cc];
__device__ __half g_ao [Mrows*Cc];
__device__ float g_proj[Mrows*Cc];
__device__ float g_u   [Mrows*Kk];
__device__ float g_y   [Mrows*Kk];
__device__ float g_tg  [Mrows*Kk];
__device__ float g_trn [Mrows*Cc];
__device__ float g_gate[Mrows];
__device__ float g_x1  [Mrows*Cc];
__device__ float g_f1  [(size_t)Mrows*DFFf];
__device__ __half g_f1h[(size_t)Mrows*DFFf];
// half weight copies
__device__ __half g_wq [3*Cc*Cc];
__device__ __half g_wp [Cc*Cc];
__device__ __half g_wg [(size_t)DFFf*Cc];
__device__ __half g_wu [(size_t)DFFf*Cc];
__device__ __half g_wd [(size_t)Cc*DFFf];

// ---------------- common PTX helpers ----------------
__device__ __forceinline__ void cp_async16(unsigned sa, const void* gp) {
    asm volatile("cp.async.cg.shared.global [%0], [%1], 16;" :: "r"(sa), "l"(gp));
}
__device__ __forceinline__ void cp_commit() {
    asm volatile("cp.async.commit_group;");
}
template<int N>
__device__ __forceinline__ void cp_wait() {
    asm volatile("cp.async.wait_group %0;" :: "n"(N));
}
__device__ __forceinline__ void mma_f16(float* d, const unsigned* a, const unsigned* b) {
    asm volatile(
        "mma.sync.aligned.m16n8k16.row.col.f32.f16.f16.f32 "
        "{%0,%1,%2,%3}, {%4,%5,%6,%7}, {%8,%9}, {%0,%1,%2,%3};"
        : "+f"(d[0]), "+f"(d[1]), "+f"(d[2]), "+f"(d[3])
        : "r"(a[0]), "r"(a[1]), "r"(a[2]), "r"(a[3]), "r"(b[0]), "r"(b[1]));
}
__device__ __forceinline__ void ldsm_x4(unsigned& r0, unsigned& r1, unsigned& r2, unsigned& r3,
                                        unsigned addr) {
    asm volatile("ldmatrix.sync.aligned.m8n8.x4.shared.b16 {%0,%1,%2,%3}, [%4];"
                 : "=r"(r0), "=r"(r1), "=r"(r2), "=r"(r3) : "r"(addr));
}
__device__ __forceinline__ void ldsm_x4_t(unsigned& r0, unsigned& r1, unsigned& r2, unsigned& r3,
                                          unsigned addr) {
    asm volatile("ldmatrix.sync.aligned.m8n8.x4.trans.shared.b16 {%0,%1,%2,%3}, [%4];"
                 : "=r"(r0), "=r"(r1), "=r"(r2), "=r"(r3) : "r"(addr));
}

// ---------------- merged weight half pre-round (one launch for all 5) ----------------
#define RQ_N (3*Cc*Cc/4)
#define RP_N (Cc*Cc/4)
#define RF_N (DFFf*Cc/4)
#define R_TOT (RQ_N + RP_N + 3*RF_N)
__global__ void round_all_kernel(const float* __restrict__ qw, __half* __restrict__ dq,
                                 const float* __restrict__ pw, __half* __restrict__ dp,
                                 const float* __restrict__ gw, __half* __restrict__ dg,
                                 const float* __restrict__ uw, __half* __restrict__ du,
                                 const float* __restrict__ dw, __half* __restrict__ dd) {
    int idx = blockIdx.x * blockDim.x + threadIdx.x;
    if (idx >= R_TOT) return;
    const float* in; __half* out; int base;
    if (idx < RQ_N)                       { in = qw; out = dq; base = 0; }
    else if (idx < RQ_N + RP_N)           { in = pw; out = dp; base = RQ_N; }
    else if (idx < RQ_N + RP_N + RF_N)    { in = gw; out = dg; base = RQ_N + RP_N; }
    else if (idx < RQ_N + RP_N + 2*RF_N)  { in = uw; out = du; base = RQ_N + RP_N + RF_N; }
    else                                  { in = dw; out = dd; base = RQ_N + RP_N + 2*RF_N; }
    int i = idx - base;
    float4 v = ((const float4*)in)[i];
    ((__half2*)out)[i*2]     = __floats2half2_rn(v.x, v.y);
    ((__half2*)out)[i*2 + 1] = __floats2half2_rn(v.z, v.w);
}

// ---------------- fused RMSNorm + scalar gate ----------------
__global__ void rms_gate_kernel(const float* __restrict__ x, const float* __restrict__ w,
                                const float* __restrict__ gw, const float* __restrict__ gb,
                                __half* __restrict__ o, float* __restrict__ g) {
    int row = blockIdx.x;
    int tid = threadIdx.x;
    const float4* xr = (const float4*)(x + (size_t)row * Cc);
    float4 v = xr[tid];
    float s = v.x*v.x + v.y*v.y + v.z*v.z + v.w*v.w;
    __shared__ float red[8];
    int lane = tid & 31, warp = tid >> 5;
    #pragma unroll
    for (int o2 = 16; o2; o2 >>= 1) s += __shfl_xor_sync(0xffffffffu, s, o2);
    if (lane == 0) red[warp] = s;
    __syncthreads();
    if (warp == 0) {
        float t = (lane < 8) ? red[lane] : 0.f;
        #pragma unroll
        for (int o2 = 4; o2; o2 >>= 1) t += __shfl_xor_sync(0xffffffffu, t, o2);
        if (lane == 0) red[0] = t;
    }
    __syncthreads();
    float inv = rsqrtf(red[0] * (1.0f / Cc) + 1e-6f);
    float4 wv = ((const float4*)w)[tid];
    float h0 = v.x*inv*wv.x, h1 = v.y*inv*wv.y, h2 = v.z*inv*wv.z, h3 = v.w*inv*wv.w;
    __half2* op = (__half2*)(o + (size_t)row * Cc + tid * 4);
    op[0] = __floats2half2_rn(h0, h1);
    op[1] = __floats2half2_rn(h2, h3);
    float4 gv = ((const float4*)gw)[tid];
    float sg = h0*gv.x + h1*gv.y + h2*gv.z + h3*gv.w;
    __syncthreads();
    #pragma unroll
    for (int o2 = 16; o2; o2 >>= 1) sg += __shfl_xor_sync(0xffffffffu, sg, o2);
    if (lane == 0) red[warp] = sg;
    __syncthreads();
    if (tid == 0) {
        float t = 0.f;
        #pragma unroll
        for (int i = 0; i < 8; i++) t += red[i];
        g[row] = 1.f / (1.f + __expf(-(t + gb[0])));
    }
}

// ---------------- fused mix + RMSNorm (x1 float, h half) ----------------
__global__ void mix_rms_kernel(const float* __restrict__ x, const float* __restrict__ ap,
                               const float* __restrict__ trn, const float* __restrict__ g,
                               const float* __restrict__ w,
                               float* __restrict__ x1, __half* __restrict__ h) {
    int row = blockIdx.x;
    int tid = threadIdx.x;
    size_t off = (size_t)row * Cc / 4 + tid;
    float gg = g[row];
    float og = 1.f - gg;
    float4 xv = ((const float4*)x)[off];
    float4 av = ((const float4*)ap)[off];
    float4 tv = ((const float4*)trn)[off];
    float4 v = make_float4(xv.x + gg*av.x + og*tv.x,
                           xv.y + gg*av.y + og*tv.y,
                           xv.z + gg*av.z + og*tv.z,
                           xv.w + gg*av.w + og*tv.w);
    ((float4*)x1)[off] = v;
    float s = v.x*v.x + v.y*v.y + v.z*v.z + v.w*v.w;
    __shared__ float red[8];
    int lane = tid & 31, warp = tid >> 5;
    #pragma unroll
    for (int o2 = 16; o2; o2 >>= 1) s += __shfl_xor_sync(0xffffffffu, s, o2);
    if (lane == 0) red[warp] = s;
    __syncthreads();
    if (warp == 0) {
        float t = (lane < 8) ? red[lane] : 0.f;
        #pragma unroll
        for (int o2 = 4; o2; o2 >>= 1) t += __shfl_xor_sync(0xffffffffu, t, o2);
        if (lane == 0) red[0] = t;
    }
    __syncthreads();
    float inv = rsqrtf(red[0] * (1.0f / Cc) + 1e-6f);
    float4 wv = ((const float4*)w)[tid];
    __half2* op = (__half2*)(h + (size_t)row * Cc + tid * 4);
    op[0] = __floats2half2_rn(v.x*inv*wv.x, v.y*inv*wv.y);
    op[1] = __floats2half2_rn(v.z*inv*wv.z, v.w*inv*wv.w);
}

// ---------------- FP16 GEMM: CTA 128x256, warp tile 64x64, 3-stage cp.async ----------------
#define T2M 128
#define T2N 256
#define TBK 32
#define TLDKH 40
#define H2_ABUF (128*TLDKH*2)     // 10240 B per A stage
#define H2_WBUF (256*TLDKH*2)     // 20480 B per W stage
#define H2_SMEM (3 * (H2_ABUF + H2_WBUF))   // 92160

// EPI: 0 none->f32, 1 +bias->f32, 2 +res(f32)->f32, 3 silu(res f32)*acc->half, 4 +bias->half
template<int EPI>
__global__ void __launch_bounds__(256, 1)
hgemm(const __half* __restrict__ A, const __half* __restrict__ W,
      const float* __restrict__ bias, const float* __restrict__ res,
      void* __restrict__ Cv, int M, int N, int Kd) {
    extern __shared__ __half hsm[];
    __half* Abase = hsm;                         // 3 x 128 x 40
    __half* Wbase = hsm + 3 * 128 * TLDKH;       // 3 x 256 x 40
    int tid = threadIdx.x;
    int lane = tid & 31, wid = tid >> 5;
    int g = lane >> 2, t = lane & 3;
    int l8 = lane & 7, sel = lane >> 3;
    int wm = wid & 1, wn = wid >> 1;             // 2 x 4 warps, warp tile 64(m) x 64(n)
    int bm = blockIdx.y, bn = blockIdx.x;
    const __half* Ap = A + (size_t)(bm * T2M) * Kd;
    const __half* Wp = W + (size_t)(bn * T2N) * Kd;
    int lrA = tid >> 1;              // 0..127
    int cuA = (tid & 1) * 2;         // 16B unit 0 or 2

    unsigned a_st = (unsigned)__cvta_generic_to_shared(&Abase[lrA*TLDKH + cuA*8]);
    unsigned w_st = (unsigned)__cvta_generic_to_shared(&Wbase[(size_t)tid*TLDKH]);
    unsigned a_la[4], w_la[4];
    #pragma unroll
    for (int mi = 0; mi < 4; mi++)
        a_la[mi] = (unsigned)__cvta_generic_to_shared(
            &Abase[(wm*64 + mi*16 + (sel&1)*8 + l8)*TLDKH + (sel>>1)*8]);
    #pragma unroll
    for (int p = 0; p < 4; p++)
        w_la[p] = (unsigned)__cvta_generic_to_shared(
            &Wbase[(wn*64 + p*16 + (sel>>1)*8 + l8)*TLDKH + (sel&1)*8]);

    int niter = Kd / TBK;
    #pragma unroll
    for (int s = 0; s < 2; s++) {
        const __half* ga = Ap + (size_t)lrA * Kd + s*TBK + cuA * 8;
        cp_async16(a_st + s*H2_ABUF, ga);
        cp_async16(a_st + s*H2_ABUF + 16, ga + 8);
        const __half* gw = Wp + (size_t)tid * Kd + s*TBK;
        #pragma unroll
        for (int cu = 0; cu < 4; cu++)
            cp_async16(w_st + s*H2_WBUF + cu*16, gw + cu*8);
        cp_commit();
    }

    float acc[4][8][4];
    #pragma unroll
    for (int mi = 0; mi < 4; mi++)
        #pragma unroll
        for (int ni = 0; ni < 8; ni++)
            #pragma unroll
            for (int j = 0; j < 4; j++) acc[mi][ni][j] = 0.f;

    unsigned coA = 0, coW = 0;
    for (int it = 0; it < niter; it++) {
        if (it + 1 < niter) cp_wait<1>(); else cp_wait<0>();
        __syncthreads();
        #pragma unroll
        for (int ks = 0; ks < 2; ks++) {
            unsigned koff = ks * 32;
            unsigned afr[4][4];
            #pragma unroll
            for (int mi = 0; mi < 4; mi++)
                ldsm_x4(afr[mi][0], afr[mi][1], afr[mi][2], afr[mi][3],
                        a_la[mi] + coA + koff);
            unsigned bfr[8][2];
            #pragma unroll
            for (int p = 0; p < 4; p++)
                ldsm_x4(bfr[2*p][0], bfr[2*p][1], bfr[2*p+1][0], bfr[2*p+1][1],
                        w_la[p] + coW + koff);
            #pragma unroll
            for (int mi = 0; mi < 4; mi++)
                #pragma unroll
                for (int ni = 0; ni < 8; ni++)
                    mma_f16(acc[mi][ni], afr[mi], bfr[ni]);
        }
        if (it + 2 < niter) {
            unsigned sA = coA + 2*H2_ABUF; if (sA >= 3*H2_ABUF) sA -= 3*H2_ABUF;
            unsigned sW = coW + 2*H2_WBUF; if (sW >= 3*H2_WBUF) sW -= 3*H2_WBUF;
            int k0 = (it + 2) * TBK;
            const __half* ga = Ap + (size_t)lrA * Kd + k0 + cuA * 8;
            cp_async16(a_st + sA, ga);
            cp_async16(a_st + sA + 16, ga + 8);
            const __half* gw = Wp + (size_t)tid * Kd + k0;
            #pragma unroll
            for (int cu = 0; cu < 4; cu++)
                cp_async16(w_st + sW + cu*16, gw + cu*8);
            cp_commit();
        }
        coA += H2_ABUF; if (coA == 3*H2_ABUF) coA = 0;
        coW += H2_WBUF; if (coW == 3*H2_WBUF) coW = 0;
    }

    float* C = (float*)Cv;
    __half* Ch = (__half*)Cv;
    #pragma unroll
    for (int mi = 0; mi < 4; mi++) {
        #pragma unroll
        for (int ni = 0; ni < 8; ni++) {
            int row = bm*T2M + wm*64 + mi*16 + g;
            int col = bn*T2N + wn*64 + ni*8 + 2*t;
            float v0 = acc[mi][ni][0], v1 = acc[mi][ni][1];
            float v2 = acc[mi][ni][2], v3 = acc[mi][ni][3];
            if (EPI == 1 || EPI == 4) {
                float b0 = bias[col], b1 = bias[col + 1];
                v0 += b0; v1 += b1; v2 += b0; v3 += b1;
            }
            if (EPI == 2) {
                const float* r0 = res + (size_t)row * N + col;
                const float* r1 = res + (size_t)(row + 8) * N + col;
                v0 += r0[0]; v1 += r0[1]; v2 += r1[0]; v3 += r1[1];
            }
            if (EPI == 3) {
                const float* r0 = res + (size_t)row * N + col;
                const float* r1 = res + (size_t)(row + 8) * N + col;
                float s0 = r0[0], s1 = r0[1], s2 = r1[0], s3 = r1[1];
                v0 = s0 / (1.f + __expf(-s0)) * v0;
                v1 = s1 / (1.f + __expf(-s1)) * v1;
                v2 = s2 / (1.f + __expf(-s2)) * v2;
                v3 = s3 / (1.f + __expf(-s3)) * v3;
            }
            if (EPI == 3 || EPI == 4) {
                *(__half2*)&Ch[(size_t)row * N + col]       = __floats2half2_rn(v0, v1);
                *(__half2*)&Ch[(size_t)(row + 8) * N + col] = __floats2half2_rn(v2, v3);
            } else {
                *(float2*)&C[(size_t)row * N + col]       = make_float2(v0, v1);
                *(float2*)&C[(size_t)(row + 8) * N + col] = make_float2(v2, v3);
            }
        }
    }
}

// ---------------- MMA windowed attention (half scores; 69 KB smem, 3 CTAs/SM) ----------------
#define QT 64
#define NJ 384
#define PHL 392
#define AT_QH   0
#define AT_KV   9216
#define AT_PH   18432
#define ATTN_SMEM (18432 + 64*PHL*2)   // 68608

__global__ void __launch_bounds__(256)
attn_mma(const __half* __restrict__ qkv, __half* __restrict__ ao) {
    extern __shared__ char smraw[];
    __half* Qh  = (__half*)(smraw + AT_QH);
    __half* KVh = (__half*)(smraw + AT_KV);
    __half* Ph  = (__half*)(smraw + AT_PH);

    int q0 = blockIdx.x * QT;
    int h = blockIdx.y, b = blockIdx.z;
    int tid = threadIdx.x;
    int lane = tid & 31, wid = tid >> 5;
    int wm = wid & 3, wn = wid >> 2;
    int l8 = lane & 7, sel = lane >> 3;
    int g = lane >> 2, t = lane & 3;
    const size_t rs = 3 * Cc;
    const __half* qbase = qkv + (size_t)b * Tt * rs + h * DHd;
    int kbase = q0 - 256;

    for (int i = tid; i < 64*8; i += 256) {
        int r = i >> 3, c8 = (i & 7) * 8;
        *(uint4*)&Qh[r*72 + c8] = *(const uint4*)(qbase + (size_t)(q0 + r) * rs + c8);
    }

    unsigned q_la = (unsigned)__cvta_generic_to_shared(
        &Qh[(wm*16 + (sel&1)*8 + l8)*72 + (sel>>1)*8]);
    unsigned k_la[2];
    #pragma unroll
    for (int p = 0; p < 2; p++)
        k_la[p] = (unsigned)__cvta_generic_to_shared(
            &KVh[(wn*32 + p*16 + (sel>>1)*8 + l8)*72 + (sel&1)*8]);
    unsigned v_la[2];
    #pragma unroll
    for (int p = 0; p < 2; p++)
        v_la[p] = (unsigned)__cvta_generic_to_shared(
            &KVh[((sel&1)*8 + l8)*72 + wn*32 + p*16 + (sel>>1)*8]);
    unsigned ph_la = (unsigned)__cvta_generic_to_shared(
        &Ph[(wm*16 + (sel&1)*8 + l8)*PHL + (sel>>1)*8]);

    // ---- phase 1: scores (half; masked = -60000) ----
    for (int cc = 0; cc < 6; cc++) {
        for (int i = tid; i < 64*8; i += 256) {
            int r = i >> 3, c8 = (i & 7) * 8;
            int kg = kbase + cc*64 + r;
            uint4 v = make_uint4(0, 0, 0, 0);
            if (kg >= 0 && kg < Tt)
                v = *(const uint4*)(qbase + Cc + (size_t)kg * rs + c8);
            *(uint4*)&KVh[r*72 + c8] = v;
        }
        __syncthreads();
        float acc[4][4] = {};
        #pragma unroll
        for (int ks = 0; ks < 4; ks++) {
            unsigned koff = ks * 32;
            unsigned af[4];
            ldsm_x4(af[0], af[1], af[2], af[3], q_la + koff);
            unsigned bf[4][2];
            #pragma unroll
            for (int p = 0; p < 2; p++)
                ldsm_x4(bf[2*p][0], bf[2*p][1], bf[2*p+1][0], bf[2*p+1][1], k_la[p] + koff);
            #pragma unroll
            for (int ni = 0; ni < 4; ni++)
                mma_f16(acc[ni], af, bf[ni]);
        }
        #pragma unroll
        for (int ni = 0; ni < 4; ni++) {
            int col = wn*32 + ni*8 + 2*t;
            int j0 = cc*64 + col;
            #pragma unroll
            for (int hh = 0; hh < 2; hh++) {
                int qi = wm*16 + g + hh*8;
                float v0 = acc[ni][2*hh]   * 0.125f;
                float v1 = acc[ni][2*hh+1] * 0.125f;
                bool ok0 = (j0   >= qi + 1) && (j0   <= qi + 256) && (kbase + j0   >= 0);
                bool ok1 = (j0+1 >= qi + 1) && (j0+1 <= qi + 256) && (kbase + j0+1 >= 0);
                *(__half2*)&Ph[qi*PHL + j0] =
                    __floats2half2_rn(ok0 ? v0 : -60000.f, ok1 ? v1 : -60000.f);
            }
        }
        __syncthreads();
    }

    // ---- phase 2: softmax in fp32 regs ----
    for (int q = wid; q < 64; q += 8) {
        float rv[12];
        #pragma unroll
        for (int jj = 0; jj < 12; jj++)
            rv[jj] = __half2float(Ph[q*PHL + lane + jj*32]);
        float m = rv[0];
        #pragma unroll
        for (int jj = 1; jj < 12; jj++) m = fmaxf(m, rv[jj]);
        #pragma unroll
        for (int o2 = 16; o2; o2 >>= 1) m = fmaxf(m, __shfl_xor_sync(0xffffffffu, m, o2));
        float s = 0.f;
        #pragma unroll
        for (int jj = 0; jj < 12; jj++) {
            rv[jj] = __expf(rv[jj] - m);
            s += rv[jj];
        }
        #pragma unroll
        for (int o2 = 16; o2; o2 >>= 1) s += __shfl_xor_sync(0xffffffffu, s, o2);
        float inv = 1.0f / s;
        #pragma unroll
        for (int jj = 0; jj < 12; jj++)
            Ph[q*PHL + lane + jj*32] = __float2half(rv[jj] * inv);
    }
    __syncthreads();

    // ---- phase 3: AV via MMA ----
    float oacc[4][4] = {};
    for (int cc = 0; cc < 6; cc++) {
        for (int i = tid; i < 64*8; i += 256) {
            int r = i >> 3, c8 = (i & 7) * 8;
            int kg = kbase + cc*64 + r;
            uint4 v = make_uint4(0, 0, 0, 0);
            if (kg >= 0 && kg < Tt)
                v = *(const uint4*)(qbase + 2*Cc + (size_t)kg * rs + c8);
            *(uint4*)&KVh[r*72 + c8] = v;
        }
        __syncthreads();
        #pragma unroll
        for (int ks = 0; ks < 4; ks++) {
            unsigned af[4];
            ldsm_x4(af[0], af[1], af[2], af[3], ph_la + cc*128 + ks*32);
            unsigned bf[4][2];
            #pragma unroll
            for (int p = 0; p < 2; p++)
                ldsm_x4_t(bf[2*p][0], bf[2*p][1], bf[2*p+1][0], bf[2*p+1][1],
                          v_la[p] + ks * (16*72*2));
            #pragma unroll
            for (int ni = 0; ni < 4; ni++)
                mma_f16(oacc[ni], af, bf[ni]);
        }
        __syncthreads();
    }

    #pragma unroll
    for (int ni = 0; ni < 4; ni++) {
        int col = wn*32 + ni*8 + 2*t;
        #pragma unroll
        for (int hh = 0; hh < 2; hh++) {
            int q = wm*16 + g + hh*8;
            *(__half2*)&ao[(size_t)(b*Tt + q0 + q)*Cc + h*DHd + col] =
                __floats2half2_rn(oacc[ni][2*hh], oacc[ni][2*hh+1]);
        }
    }
}

// ---------------- merged skinny GEMM ----------------
__global__ void gemm_skinny2(const __half* __restrict__ A,
                             const float* __restrict__ W1, const float* __restrict__ W2,
                             const float* __restrict__ b2,
                             float* __restrict__ U, float* __restrict__ TG, int Kd) {
    __shared__ float As[16][64];
    __shared__ float Ws[2][32][65];
    int tx = threadIdx.x, ty = threadIdx.y;
    int tid = ty * 32 + tx;
    int m0 = blockIdx.x * 16;
    float u0 = 0.f, u1 = 0.f, t0a = 0.f, t1a = 0.f;
    for (int k0 = 0; k0 < Kd; k0 += 64) {
        int r = tid >> 4, c4 = (tid & 15) * 4;
        const __half2* ap = (const __half2*)&A[(size_t)(m0 + r) * Kd + k0 + c4];
        float2 f0 = __half22float2(ap[0]);
        float2 f1 = __half22float2(ap[1]);
        As[r][c4+0] = f0.x; As[r][c4+1] = f0.y; As[r][c4+2] = f1.x; As[r][c4+3] = f1.y;
        int r2 = tid >> 3, c8 = (tid & 7) * 8;
        float4 w0 = *(const float4*)&W1[(size_t)r2 * Kd + k0 + c8];
        float4 w1 = *(const float4*)&W1[(size_t)r2 * Kd + k0 + c8 + 4];
        Ws[0][r2][c8+0]=w0.x; Ws[0][r2][c8+1]=w0.y; Ws[0][r2][c8+2]=w0.z; Ws[0][r2][c8+3]=w0.w;
        Ws[0][r2][c8+4]=w1.x; Ws[0][r2][c8+5]=w1.y; Ws[0][r2][c8+6]=w1.z; Ws[0][r2][c8+7]=w1.w;
        float4 x0 = *(const float4*)&W2[(size_t)r2 * Kd + k0 + c8];
        float4 x1 = *(const float4*)&W2[(size_t)r2 * Kd + k0 + c8 + 4];
        Ws[1][r2][c8+0]=x0.x; Ws[1][r2][c8+1]=x0.y; Ws[1][r2][c8+2]=x0.z; Ws[1][r2][c8+3]=x0.w;
        Ws[1][r2][c8+4]=x1.x; Ws[1][r2][c8+5]=x1.y; Ws[1][r2][c8+6]=x1.z; Ws[1][r2][c8+7]=x1.w;
        __syncthreads();
        #pragma unroll
        for (int kk = 0; kk < 64; kk++) {
            float a0 = As[ty][kk], a1 = As[ty + 8][kk];
            float wv1 = Ws[0][tx][kk], wv2 = Ws[1][tx][kk];
            u0 += a0 * wv1;  u1 += a1 * wv1;
            t0a += a0 * wv2; t1a += a1 * wv2;
        }
        __syncthreads();
    }
    U[(size_t)(m0 + ty) * Kk + tx]     = u0;
    U[(size_t)(m0 + ty + 8) * Kk + tx] = u1;
    float bb = b2[tx];
    TG[(size_t)(m0 + ty) * Kk + tx]     = 1.f / (1.f + __expf(-(t0a + bb)));
    TG[(size_t)(m0 + ty + 8) * Kk + tx] = 1.f / (1.f + __expf(-(t1a + bb)));
}

// ---------------- chunked parallel oscillator scan ----------------
__global__ void scan_kernel(const float* __restrict__ u, const float* __restrict__ a_logit,
                            const float* __restrict__ theta, float* __restrict__ y) {
    __shared__ float ssr[32][33], ssi[32][33];
    int b = blockIdx.x;
    int tid = threadIdx.x;
    int k = tid & 31, c = tid >> 5;
    float a  = 1.f / (1.f + __expf(-a_logit[k]));
    float ct = cosf(theta[k]), st = sinf(theta[k]);
    const float* up = u + (size_t)b * Tt * Kk + k;
    int t0 = c * 64;

    float sr = 0.f, si = 0.f;
    for (int i = 0; i < 64; i++) {
        float ut = up[(size_t)(t0 + i) * Kk];
        float nsr = a * (ct * sr - st * si) + ut;
        float nsi = a * (st * sr + ct * si);
        sr = nsr; si = nsi;
    }
    ssr[c][k] = sr; ssi[c][k] = si;
    __syncthreads();

    if (tid < 32) {
        int kq = tid;
        float aq = 1.f / (1.f + __expf(-a_logit[kq]));
        float a64 = __powf(aq, 64.f);
        float th = theta[kq];
        float c64 = cosf(64.f * th), s64 = sinf(64.f * th);
        float M00 = a64 * c64, M01 = -a64 * s64;
        float M10 = a64 * s64, M11 =  a64 * c64;
        float cr = 0.f, ci = 0.f;
        for (int cc = 0; cc < 32; cc++) {
            float lr = ssr[cc][kq], li = ssi[cc][kq];
            ssr[cc][kq] = cr; ssi[cc][kq] = ci;
            float nr = M00 * cr + M01 * ci + lr;
            float ni = M10 * cr + M11 * ci + li;
            cr = nr; ci = ni;
        }
    }
    __syncthreads();

    sr = ssr[c][k]; si = ssi[c][k];
    float* yp = y + (size_t)b * Tt * Kk + k;
    for (int i = 0; i < 64; i++) {
        float ut = up[(size_t)(t0 + i) * Kk];
        float nsr = a * (ct * sr - st * si) + ut;
        float nsi = a * (st * sr + ct * si);
        sr = nsr; si = nsi;
        yp[(size_t)(t0 + i) * Kk] = sr;
    }
}

// ---------------- trn_out ----------------
__global__ void trn_out_kernel(const float* __restrict__ tg, const float* __restrict__ y,
                               const float* __restrict__ wout, const float* __restrict__ scale_p,
                               float* __restrict__ out) {
    __shared__ float Zs[16][33];
    __shared__ float Ws[64][33];
    int tx = threadIdx.x, ty = threadIdx.y;
    int tid = ty * 64 + tx;
    int m0 = blockIdx.x * 16, c0 = blockIdx.y * 64;
    for (int i = tid; i < 16 * Kk; i += 256) {
        int r = i >> 5, k = i & 31;
        size_t off = (size_t)(m0 + r) * Kk + k;
        Zs[r][k] = tg[off] * y[off];
    }
    for (int i = tid; i < 64 * Kk; i += 256) {
        int r = i >> 5, k = i & 31;
        Ws[r][k] = wout[(size_t)(c0 + r) * Kk + k];
    }
    __syncthreads();
    float scale = scale_p[0];
    float acc[4] = {0.f, 0.f, 0.f, 0.f};
    #pragma unroll
    for (int k = 0; k < Kk; k++) {
        float wv = Ws[tx][k];
        acc[0] += Zs[ty][k]      * wv;
        acc[1] += Zs[ty + 4][k]  * wv;
        acc[2] += Zs[ty + 8][k]  * wv;
        acc[3] += Zs[ty + 12][k] * wv;
    }
    #pragma unroll
    for (int r = 0; r < 4; r++)
        out[(size_t)(m0 + ty + 4 * r) * Cc + c0 + tx] = acc[r] * scale;
}

// ---------------- launch ----------------
extern "C" void kernel_launch(void* const* d_in, const int* in_sizes, int n_in,
                              void* d_out, int out_size) {
    const float* x          = (const float*)d_in[0];
    const float* norm1_w    = (const float*)d_in[1];
    const float* qkv_w      = (const float*)d_in[2];
    const float* qkv_b      = (const float*)d_in[3];
    const float* proj_w     = (const float*)d_in[4];
    const float* proj_b     = (const float*)d_in[5];
    const float* gate_w     = (const float*)d_in[6];
    const float* gate_b     = (const float*)d_in[7];
    const float* trn_win    = (const float*)d_in[8];
    const float* trn_wout   = (const float*)d_in[9];
    const float* trn_gate_w = (const float*)d_in[10];
    const float* trn_gate_b = (const float*)d_in[11];
    const float* trn_a      = (const float*)d_in[12];
    const float* trn_theta  = (const float*)d_in[13];
    const float* trn_scale  = (const float*)d_in[14];
    const float* norm2_w    = (const float*)d_in[15];
    const float* ffn_gate_w = (const float*)d_in[16];
    const float* ffn_up_w   = (const float*)d_in[17];
    const float* ffn_down_w = (const float*)d_in[18];
    float* out = (float*)d_out;

    __half *h, *qkv, *ao, *f1h, *wq, *wp, *wg, *wu, *wd;
    float *proj, *u, *y, *tg, *trn, *gate, *x1, *f1;
    cudaGetSymbolAddress((void**)&h,    g_h);
    cudaGetSymbolAddress((void**)&qkv,  g_qkv);
    cudaGetSymbolAddress((void**)&ao,   g_ao);
    cudaGetSymbolAddress((void**)&proj, g_proj);
    cudaGetSymbolAddress((void**)&u,    g_u);
    cudaGetSymbolAddress((void**)&y,    g_y);
    cudaGetSymbolAddress((void**)&tg,   g_tg);
    cudaGetSymbolAddress((void**)&trn,  g_trn);
    cudaGetSymbolAddress((void**)&gate, g_gate);
    cudaGetSymbolAddress((void**)&x1,   g_x1);
    cudaGetSymbolAddress((void**)&f1,   g_f1);
    cudaGetSymbolAddress((void**)&f1h,  g_f1h);
    cudaGetSymbolAddress((void**)&wq,   g_wq);
    cudaGetSymbolAddress((void**)&wp,   g_wp);
    cudaGetSymbolAddress((void**)&wg,   g_wg);
    cudaGetSymbolAddress((void**)&wu,   g_wu);
    cudaGetSymbolAddress((void**)&wd,   g_wd);

    cudaFuncSetAttribute(attn_mma, cudaFuncAttributeMaxDynamicSharedMemorySize, ATTN_SMEM);
    cudaFuncSetAttribute(hgemm<0>, cudaFuncAttributeMaxDynamicSharedMemorySize, H2_SMEM);
    cudaFuncSetAttribute(hgemm<1>, cudaFuncAttributeMaxDynamicSharedMemorySize, H2_SMEM);
    cudaFuncSetAttribute(hgemm<2>, cudaFuncAttributeMaxDynamicSharedMemorySize, H2_SMEM);
    cudaFuncSetAttribute(hgemm<3>, cudaFuncAttributeMaxDynamicSharedMemorySize, H2_SMEM);
    cudaFuncSetAttribute(hgemm<4>, cudaFuncAttributeMaxDynamicSharedMemorySize, H2_SMEM);

    // 0) pre-convert all weights to half (single launch)
    round_all_kernel<<<(R_TOT + 255) / 256, 256>>>(qkv_w, wq, proj_w, wp,
                                                   ffn_gate_w, wg, ffn_up_w, wu,
                                                   ffn_down_w, wd);

    // 1) h = rms(x, norm1_w) [half] + gate scalar (fused)
    rms_gate_kernel<<<Mrows, 256>>>(x, norm1_w, gate_w, gate_b, h, gate);
    // 2) qkv = h @ qkv_w^T + qkv_b [half out]
    hgemm<4><<<dim3(3 * Cc / T2N, Mrows / T2M), 256, H2_SMEM>>>(h, wq, qkv_b, nullptr, qkv, Mrows, 3 * Cc, Cc);
    // 3) attention (MMA, half scores, 3 CTAs/SM)
    attn_mma<<<dim3(Tt / QT, Hh, Bb), 256, ATTN_SMEM>>>(qkv, ao);
    // 4) proj [float out]
    hgemm<1><<<dim3(Cc / T2N, Mrows / T2M), 256, H2_SMEM>>>(ao, wp, proj_b, nullptr, proj, Mrows, Cc, Cc);
    // 5) TRN branch
    gemm_skinny2<<<Mrows / 16, dim3(32, 8)>>>(h, trn_win, trn_gate_w, trn_gate_b, u, tg, Cc);
    scan_kernel<<<Bb, 1024>>>(u, trn_a, trn_theta, y);
    trn_out_kernel<<<dim3(Mrows / 16, Cc / 64), dim3(64, 4)>>>(tg, y, trn_wout, trn_scale, trn);
    // 6) fused mix+rms2
    mix_rms_kernel<<<Mrows, 256>>>(x, proj, trn, gate, norm2_w, x1, h);
    // 7) FFN (f1 float)
    hgemm<0><<<dim3(DFFf / T2N, Mrows / T2M), 256, H2_SMEM>>>(h, wg, nullptr, nullptr, f1, Mrows, DFFf, Cc);
    hgemm<3><<<dim3(DFFf / T2N, Mrows / T2M), 256, H2_SMEM>>>(h, wu, nullptr, f1, f1h, Mrows, DFFf, Cc);
    // 8) out = f1h @ Wd^T + x1
    hgemm<2><<<dim3(Cc / T2N, Mrows / T2M), 256, H2_SMEM>>>(f1h, wd, nullptr, x1, out, Mrows, Cc, DFFf);
}

// round 16
// speedup vs baseline: 1.0902x; 1.0902x over previous
#include <cuda_runtime.h>
#include <cuda_fp16.h>
#include <math.h>
#include <stdint.h>

#define Bb   2
#define Tt   2048
#define Cc   1024
#define Hh   16
#define DHd  64
#define WINw 256
#define Kk   32
#define DFFf 4096
#define Mrows (Bb*Tt)   // 4096

// ---------------- scratch ----------------
__device__ __half g_h  [Mrows*Cc];
__device__ __half g_qkv[Mrows*3*Cc];
__device__ __half g_ao [Mrows*Cc];
__device__ float g_proj[Mrows*Cc];
__device__ float g_u   [Mrows*Kk];
__device__ float g_y   [Mrows*Kk];
__device__ float g_tg  [Mrows*Kk];
__device__ float g_trn [Mrows*Cc];
__device__ float g_gate[Mrows];
__device__ float g_x1  [Mrows*Cc];
__device__ float g_f1  [(size_t)Mrows*DFFf];
__device__ __half g_f1h[(size_t)Mrows*DFFf];
// half weight copies
__device__ __half g_wq [3*Cc*Cc];
__device__ __half g_wp [Cc*Cc];
__device__ __half g_wg [(size_t)DFFf*Cc];
__device__ __half g_wu [(size_t)DFFf*Cc];
__device__ __half g_wd [(size_t)Cc*DFFf];

// ---------------- common PTX helpers ----------------
__device__ __forceinline__ void cp_async16(unsigned sa, const void* gp) {
    asm volatile("cp.async.cg.shared.global [%0], [%1], 16;" :: "r"(sa), "l"(gp));
}
__device__ __forceinline__ void cp_commit() {
    asm volatile("cp.async.commit_group;");
}
template<int N>
__device__ __forceinline__ void cp_wait() {
    asm volatile("cp.async.wait_group %0;" :: "n"(N));
}
__device__ __forceinline__ void mma_f16(float* d, const unsigned* a, const unsigned* b) {
    asm volatile(
        "mma.sync.aligned.m16n8k16.row.col.f32.f16.f16.f32 "
        "{%0,%1,%2,%3}, {%4,%5,%6,%7}, {%8,%9}, {%0,%1,%2,%3};"
        : "+f"(d[0]), "+f"(d[1]), "+f"(d[2]), "+f"(d[3])
        : "r"(a[0]), "r"(a[1]), "r"(a[2]), "r"(a[3]), "r"(b[0]), "r"(b[1]));
}
__device__ __forceinline__ void ldsm_x4(unsigned& r0, unsigned& r1, unsigned& r2, unsigned& r3,
                                        unsigned addr) {
    asm volatile("ldmatrix.sync.aligned.m8n8.x4.shared.b16 {%0,%1,%2,%3}, [%4];"
                 : "=r"(r0), "=r"(r1), "=r"(r2), "=r"(r3) : "r"(addr));
}
__device__ __forceinline__ void ldsm_x4_t(unsigned& r0, unsigned& r1, unsigned& r2, unsigned& r3,
                                          unsigned addr) {
    asm volatile("ldmatrix.sync.aligned.m8n8.x4.trans.shared.b16 {%0,%1,%2,%3}, [%4];"
                 : "=r"(r0), "=r"(r1), "=r"(r2), "=r"(r3) : "r"(addr));
}

// ---------------- merged weight half pre-round (one launch for all 5) ----------------
#define RQ_N (3*Cc*Cc/4)
#define RP_N (Cc*Cc/4)
#define RF_N (DFFf*Cc/4)
#define R_TOT (RQ_N + RP_N + 3*RF_N)
__global__ void round_all_kernel(const float* __restrict__ qw, __half* __restrict__ dq,
                                 const float* __restrict__ pw, __half* __restrict__ dp,
                                 const float* __restrict__ gw, __half* __restrict__ dg,
                                 const float* __restrict__ uw, __half* __restrict__ du,
                                 const float* __restrict__ dw, __half* __restrict__ dd) {
    int idx = blockIdx.x * blockDim.x + threadIdx.x;
    if (idx >= R_TOT) return;
    const float* in; __half* out; int base;
    if (idx < RQ_N)                       { in = qw; out = dq; base = 0; }
    else if (idx < RQ_N + RP_N)           { in = pw; out = dp; base = RQ_N; }
    else if (idx < RQ_N + RP_N + RF_N)    { in = gw; out = dg; base = RQ_N + RP_N; }
    else if (idx < RQ_N + RP_N + 2*RF_N)  { in = uw; out = du; base = RQ_N + RP_N + RF_N; }
    else                                  { in = dw; out = dd; base = RQ_N + RP_N + 2*RF_N; }
    int i = idx - base;
    float4 v = ((const float4*)in)[i];
    __half2 a = __floats2half2_rn(v.x, v.y);
    __half2 b = __floats2half2_rn(v.z, v.w);
    ((uint2*)out)[i] = make_uint2(*(unsigned*)&a, *(unsigned*)&b);
}

// ---------------- fused RMSNorm + scalar gate ----------------
__global__ void rms_gate_kernel(const float* __restrict__ x, const float* __restrict__ w,
                                const float* __restrict__ gw, const float* __restrict__ gb,
                                __half* __restrict__ o, float* __restrict__ g) {
    int row = blockIdx.x;
    int tid = threadIdx.x;
    const float4* xr = (const float4*)(x + (size_t)row * Cc);
    float4 v = xr[tid];
    float s = v.x*v.x + v.y*v.y + v.z*v.z + v.w*v.w;
    __shared__ float red[8];
    int lane = tid & 31, warp = tid >> 5;
    #pragma unroll
    for (int o2 = 16; o2; o2 >>= 1) s += __shfl_xor_sync(0xffffffffu, s, o2);
    if (lane == 0) red[warp] = s;
    __syncthreads();
    if (warp == 0) {
        float t = (lane < 8) ? red[lane] : 0.f;
        #pragma unroll
        for (int o2 = 4; o2; o2 >>= 1) t += __shfl_xor_sync(0xffffffffu, t, o2);
        if (lane == 0) red[0] = t;
    }
    __syncthreads();
    float inv = rsqrtf(red[0] * (1.0f / Cc) + 1e-6f);
    float4 wv = ((const float4*)w)[tid];
    float h0 = v.x*inv*wv.x, h1 = v.y*inv*wv.y, h2 = v.z*inv*wv.z, h3 = v.w*inv*wv.w;
    __half2* op = (__half2*)(o + (size_t)row * Cc + tid * 4);
    op[0] = __floats2half2_rn(h0, h1);
    op[1] = __floats2half2_rn(h2, h3);
    float4 gv = ((const float4*)gw)[tid];
    float sg = h0*gv.x + h1*gv.y + h2*gv.z + h3*gv.w;
    __syncthreads();
    #pragma unroll
    for (int o2 = 16; o2; o2 >>= 1) sg += __shfl_xor_sync(0xffffffffu, sg, o2);
    if (lane == 0) red[warp] = sg;
    __syncthreads();
    if (tid == 0) {
        float t = 0.f;
        #pragma unroll
        for (int i = 0; i < 8; i++) t += red[i];
        g[row] = 1.f / (1.f + __expf(-(t + gb[0])));
    }
}

// ---------------- fused mix + RMSNorm (x1 float, h half) ----------------
__global__ void mix_rms_kernel(const float* __restrict__ x, const float* __restrict__ ap,
                               const float* __restrict__ trn, const float* __restrict__ g,
                               const float* __restrict__ w,
                               float* __restrict__ x1, __half* __restrict__ h) {
    int row = blockIdx.x;
    int tid = threadIdx.x;
    size_t off = (size_t)row * Cc / 4 + tid;
    float gg = g[row];
    float og = 1.f - gg;
    float4 xv = ((const float4*)x)[off];
    float4 av = ((const float4*)ap)[off];
    float4 tv = ((const float4*)trn)[off];
    float4 v = make_float4(xv.x + gg*av.x + og*tv.x,
                           xv.y + gg*av.y + og*tv.y,
                           xv.z + gg*av.z + og*tv.z,
                           xv.w + gg*av.w + og*tv.w);
    ((float4*)x1)[off] = v;
    float s = v.x*v.x + v.y*v.y + v.z*v.z + v.w*v.w;
    __shared__ float red[8];
    int lane = tid & 31, warp = tid >> 5;
    #pragma unroll
    for (int o2 = 16; o2; o2 >>= 1) s += __shfl_xor_sync(0xffffffffu, s, o2);
    if (lane == 0) red[warp] = s;
    __syncthreads();
    if (warp == 0) {
        float t = (lane < 8) ? red[lane] : 0.f;
        #pragma unroll
        for (int o2 = 4; o2; o2 >>= 1) t += __shfl_xor_sync(0xffffffffu, t, o2);
        if (lane == 0) red[0] = t;
    }
    __syncthreads();
    float inv = rsqrtf(red[0] * (1.0f / Cc) + 1e-6f);
    float4 wv = ((const float4*)w)[tid];
    __half2* op = (__half2*)(h + (size_t)row * Cc + tid * 4);
    op[0] = __floats2half2_rn(v.x*inv*wv.x, v.y*inv*wv.y);
    op[1] = __floats2half2_rn(v.z*inv*wv.z, v.w*inv*wv.w);
}

// ---------------- FP16 GEMM: CTA 128x128, warp 32x64, TBK=64, 3-stage cp.async ----------------
#define TBM 128
#define TBN 128
#define TBK 64
#define TLDKH 72                       // 144-byte row pitch (LDSM conflict-free)
#define HG_BUFB (128*TLDKH*2)          // 18432 B per matrix per stage
#define HG_SMEM (3 * HG_BUFB * 2)      // 110592

// EPI: 0 none->f32, 1 +bias->f32, 2 +res(f32)->f32, 3 silu(res f32)*acc->half, 4 +bias->half
template<int EPI>
__global__ void __launch_bounds__(256, 2)
hgemm(const __half* __restrict__ A, const __half* __restrict__ W,
      const float* __restrict__ bias, const float* __restrict__ res,
      void* __restrict__ Cv, int M, int N, int Kd) {
    extern __shared__ __half hsm[];
    __half* Abase = hsm;
    __half* Wbase = hsm + 3 * 128 * TLDKH;
    int tid = threadIdx.x;
    int lane = tid & 31, wid = tid >> 5;
    int g = lane >> 2, t = lane & 3;
    int l8 = lane & 7, sel = lane >> 3;
    int wm = wid & 3, wn = wid >> 2;
    int bm = blockIdx.y, bn = blockIdx.x;
    const __half* Ap = A + (size_t)(bm * TBM) * Kd;
    const __half* Wp = W + (size_t)(bn * TBN) * Kd;
    int lr = tid >> 1;               // 0..127
    int cu0 = (tid & 1) * 4;         // 16B unit 0 or 4 (each thread does 4 units)

    unsigned a_st = (unsigned)__cvta_generic_to_shared(&Abase[lr*TLDKH + cu0*8]);
    unsigned w_st = (unsigned)__cvta_generic_to_shared(&Wbase[lr*TLDKH + cu0*8]);
    unsigned a_la[2], w_la[4];
    #pragma unroll
    for (int mi = 0; mi < 2; mi++)
        a_la[mi] = (unsigned)__cvta_generic_to_shared(
            &Abase[(wm*32 + mi*16 + (sel&1)*8 + l8)*TLDKH + (sel>>1)*8]);
    #pragma unroll
    for (int p = 0; p < 4; p++)
        w_la[p] = (unsigned)__cvta_generic_to_shared(
            &Wbase[(wn*64 + p*16 + (sel>>1)*8 + l8)*TLDKH + (sel&1)*8]);

    int niter = Kd / TBK;
    #pragma unroll
    for (int s = 0; s < 2; s++) {
        const __half* ga = Ap + (size_t)lr * Kd + s*TBK + cu0 * 8;
        const __half* gw = Wp + (size_t)lr * Kd + s*TBK + cu0 * 8;
        #pragma unroll
        for (int u = 0; u < 4; u++) {
            cp_async16(a_st + s*HG_BUFB + u*16, ga + u*8);
            cp_async16(w_st + s*HG_BUFB + u*16, gw + u*8);
        }
        cp_commit();
    }

    float acc[2][8][4];
    #pragma unroll
    for (int mi = 0; mi < 2; mi++)
        #pragma unroll
        for (int ni = 0; ni < 8; ni++)
            #pragma unroll
            for (int j = 0; j < 4; j++) acc[mi][ni][j] = 0.f;

    unsigned co = 0;
    for (int it = 0; it < niter; it++) {
        if (it + 1 < niter) cp_wait<1>(); else cp_wait<0>();
        __syncthreads();
        #pragma unroll
        for (int ks = 0; ks < 4; ks++) {
            unsigned koff = co + ks * 32;
            unsigned afr[2][4];
            #pragma unroll
            for (int mi = 0; mi < 2; mi++)
                ldsm_x4(afr[mi][0], afr[mi][1], afr[mi][2], afr[mi][3], a_la[mi] + koff);
            unsigned bfr[8][2];
            #pragma unroll
            for (int p = 0; p < 4; p++)
                ldsm_x4(bfr[2*p][0], bfr[2*p][1], bfr[2*p+1][0], bfr[2*p+1][1], w_la[p] + koff);
            #pragma unroll
            for (int mi = 0; mi < 2; mi++)
                #pragma unroll
                for (int ni = 0; ni < 8; ni++)
                    mma_f16(acc[mi][ni], afr[mi], bfr[ni]);
        }
        if (it + 2 < niter) {
            unsigned so = co + 2*HG_BUFB; if (so >= 3*HG_BUFB) so -= 3*HG_BUFB;
            int k0 = (it + 2) * TBK;
            const __half* ga = Ap + (size_t)lr * Kd + k0 + cu0 * 8;
            const __half* gw = Wp + (size_t)lr * Kd + k0 + cu0 * 8;
            #pragma unroll
            for (int u = 0; u < 4; u++) {
                cp_async16(a_st + so + u*16, ga + u*8);
                cp_async16(w_st + so + u*16, gw + u*8);
            }
            cp_commit();
        }
        co += HG_BUFB; if (co == 3*HG_BUFB) co = 0;
    }

    float* C = (float*)Cv;
    __half* Ch = (__half*)Cv;
    #pragma unroll
    for (int mi = 0; mi < 2; mi++) {
        #pragma unroll
        for (int ni = 0; ni < 8; ni++) {
            int row = bm*TBM + wm*32 + mi*16 + g;
            int col = bn*TBN + wn*64 + ni*8 + 2*t;
            float v0 = acc[mi][ni][0], v1 = acc[mi][ni][1];
            float v2 = acc[mi][ni][2], v3 = acc[mi][ni][3];
            if (EPI == 1 || EPI == 4) {
                float b0 = bias[col], b1 = bias[col + 1];
                v0 += b0; v1 += b1; v2 += b0; v3 += b1;
            }
            if (EPI == 2) {
                const float* r0 = res + (size_t)row * N + col;
                const float* r1 = res + (size_t)(row + 8) * N + col;
                v0 += r0[0]; v1 += r0[1]; v2 += r1[0]; v3 += r1[1];
            }
            if (EPI == 3) {
                const float* r0 = res + (size_t)row * N + col;
                const float* r1 = res + (size_t)(row + 8) * N + col;
                float s0 = r0[0], s1 = r0[1], s2 = r1[0], s3 = r1[1];
                v0 = s0 / (1.f + __expf(-s0)) * v0;
                v1 = s1 / (1.f + __expf(-s1)) * v1;
                v2 = s2 / (1.f + __expf(-s2)) * v2;
                v3 = s3 / (1.f + __expf(-s3)) * v3;
            }
            if (EPI == 3 || EPI == 4) {
                *(__half2*)&Ch[(size_t)row * N + col]       = __floats2half2_rn(v0, v1);
                *(__half2*)&Ch[(size_t)(row + 8) * N + col] = __floats2half2_rn(v2, v3);
            } else {
                *(float2*)&C[(size_t)row * N + col]       = make_float2(v0, v1);
                *(float2*)&C[(size_t)(row + 8) * N + col] = make_float2(v2, v3);
            }
        }
    }
}

// ---------------- MMA windowed attention (half scores; 69 KB smem, 3 CTAs/SM) ----------------
#define QT 64
#define NJ 384
#define PHL 392
#define AT_QH   0
#define AT_KV   9216
#define AT_PH   18432
#define ATTN_SMEM (18432 + 64*PHL*2)   // 68608

__global__ void __launch_bounds__(256)
attn_mma(const __half* __restrict__ qkv, __half* __restrict__ ao) {
    extern __shared__ char smraw[];
    __half* Qh  = (__half*)(smraw + AT_QH);
    __half* KVh = (__half*)(smraw + AT_KV);
    __half* Ph  = (__half*)(smraw + AT_PH);

    int q0 = blockIdx.x * QT;
    int h = blockIdx.y, b = blockIdx.z;
    int tid = threadIdx.x;
    int lane = tid & 31, wid = tid >> 5;
    int wm = wid & 3, wn = wid >> 2;
    int l8 = lane & 7, sel = lane >> 3;
    int g = lane >> 2, t = lane & 3;
    const size_t rs = 3 * Cc;
    const __half* qbase = qkv + (size_t)b * Tt * rs + h * DHd;
    int kbase = q0 - 256;

    for (int i = tid; i < 64*8; i += 256) {
        int r = i >> 3, c8 = (i & 7) * 8;
        *(uint4*)&Qh[r*72 + c8] = *(const uint4*)(qbase + (size_t)(q0 + r) * rs + c8);
    }

    unsigned q_la = (unsigned)__cvta_generic_to_shared(
        &Qh[(wm*16 + (sel&1)*8 + l8)*72 + (sel>>1)*8]);
    unsigned k_la[2];
    #pragma unroll
    for (int p = 0; p < 2; p++)
        k_la[p] = (unsigned)__cvta_generic_to_shared(
            &KVh[(wn*32 + p*16 + (sel>>1)*8 + l8)*72 + (sel&1)*8]);
    unsigned v_la[2];
    #pragma unroll
    for (int p = 0; p < 2; p++)
        v_la[p] = (unsigned)__cvta_generic_to_shared(
            &KVh[((sel&1)*8 + l8)*72 + wn*32 + p*16 + (sel>>1)*8]);
    unsigned ph_la = (unsigned)__cvta_generic_to_shared(
        &Ph[(wm*16 + (sel&1)*8 + l8)*PHL + (sel>>1)*8]);

    // ---- phase 1: scores (half; masked = -60000) ----
    for (int cc = 0; cc < 6; cc++) {
        for (int i = tid; i < 64*8; i += 256) {
            int r = i >> 3, c8 = (i & 7) * 8;
            int kg = kbase + cc*64 + r;
            uint4 v = make_uint4(0, 0, 0, 0);
            if (kg >= 0 && kg < Tt)
                v = *(const uint4*)(qbase + Cc + (size_t)kg * rs + c8);
            *(uint4*)&KVh[r*72 + c8] = v;
        }
        __syncthreads();
        float acc[4][4] = {};
        #pragma unroll
        for (int ks = 0; ks < 4; ks++) {
            unsigned koff = ks * 32;
            unsigned af[4];
            ldsm_x4(af[0], af[1], af[2], af[3], q_la + koff);
            unsigned bf[4][2];
            #pragma unroll
            for (int p = 0; p < 2; p++)
                ldsm_x4(bf[2*p][0], bf[2*p][1], bf[2*p+1][0], bf[2*p+1][1], k_la[p] + koff);
            #pragma unroll
            for (int ni = 0; ni < 4; ni++)
                mma_f16(acc[ni], af, bf[ni]);
        }
        #pragma unroll
        for (int ni = 0; ni < 4; ni++) {
            int col = wn*32 + ni*8 + 2*t;
            int j0 = cc*64 + col;
            #pragma unroll
            for (int hh = 0; hh < 2; hh++) {
                int qi = wm*16 + g + hh*8;
                float v0 = acc[ni][2*hh]   * 0.125f;
                float v1 = acc[ni][2*hh+1] * 0.125f;
                bool ok0 = (j0   >= qi + 1) && (j0   <= qi + 256) && (kbase + j0   >= 0);
                bool ok1 = (j0+1 >= qi + 1) && (j0+1 <= qi + 256) && (kbase + j0+1 >= 0);
                *(__half2*)&Ph[qi*PHL + j0] =
                    __floats2half2_rn(ok0 ? v0 : -60000.f, ok1 ? v1 : -60000.f);
            }
        }
        __syncthreads();
    }

    // ---- phase 2: softmax in fp32 regs ----
    for (int q = wid; q < 64; q += 8) {
        float rv[12];
        #pragma unroll
        for (int jj = 0; jj < 12; jj++)
            rv[jj] = __half2float(Ph[q*PHL + lane + jj*32]);
        float m = rv[0];
        #pragma unroll
        for (int jj = 1; jj < 12; jj++) m = fmaxf(m, rv[jj]);
        #pragma unroll
        for (int o2 = 16; o2; o2 >>= 1) m = fmaxf(m, __shfl_xor_sync(0xffffffffu, m, o2));
        float s = 0.f;
        #pragma unroll
        for (int jj = 0; jj < 12; jj++) {
            rv[jj] = __expf(rv[jj] - m);
            s += rv[jj];
        }
        #pragma unroll
        for (int o2 = 16; o2; o2 >>= 1) s += __shfl_xor_sync(0xffffffffu, s, o2);
        float inv = 1.0f / s;
        #pragma unroll
        for (int jj = 0; jj < 12; jj++)
            Ph[q*PHL + lane + jj*32] = __float2half(rv[jj] * inv);
    }
    __syncthreads();

    // ---- phase 3: AV via MMA ----
    float oacc[4][4] = {};
    for (int cc = 0; cc < 6; cc++) {
        for (int i = tid; i < 64*8; i += 256) {
            int r = i >> 3, c8 = (i & 7) * 8;
            int kg = kbase + cc*64 + r;
            uint4 v = make_uint4(0, 0, 0, 0);
            if (kg >= 0 && kg < Tt)
                v = *(const uint4*)(qbase + 2*Cc + (size_t)kg * rs + c8);
            *(uint4*)&KVh[r*72 + c8] = v;
        }
        __syncthreads();
        #pragma unroll
        for (int ks = 0; ks < 4; ks++) {
            unsigned af[4];
            ldsm_x4(af[0], af[1], af[2], af[3], ph_la + cc*128 + ks*32);
            unsigned bf[4][2];
            #pragma unroll
            for (int p = 0; p < 2; p++)
                ldsm_x4_t(bf[2*p][0], bf[2*p][1], bf[2*p+1][0], bf[2*p+1][1],
                          v_la[p] + ks * (16*72*2));
            #pragma unroll
            for (int ni = 0; ni < 4; ni++)
                mma_f16(oacc[ni], af, bf[ni]);
        }
        __syncthreads();
    }

    #pragma unroll
    for (int ni = 0; ni < 4; ni++) {
        int col = wn*32 + ni*8 + 2*t;
        #pragma unroll
        for (int hh = 0; hh < 2; hh++) {
            int q = wm*16 + g + hh*8;
            *(__half2*)&ao[(size_t)(b*Tt + q0 + q)*Cc + h*DHd + col] =
                __floats2half2_rn(oacc[ni][2*hh], oacc[ni][2*hh+1]);
        }
    }
}

// ---------------- merged skinny GEMM ----------------
__global__ void gemm_skinny2(const __half* __restrict__ A,
                             const float* __restrict__ W1, const float* __restrict__ W2,
                             const float* __restrict__ b2,
                             float* __restrict__ U, float* __restrict__ TG, int Kd) {
    __shared__ float As[16][64];
    __shared__ float Ws[2][32][65];
    int tx = threadIdx.x, ty = threadIdx.y;
    int tid = ty * 32 + tx;
    int m0 = blockIdx.x * 16;
    float u0 = 0.f, u1 = 0.f, t0a = 0.f, t1a = 0.f;
    for (int k0 = 0; k0 < Kd; k0 += 64) {
        int r = tid >> 4, c4 = (tid & 15) * 4;
        const __half2* ap = (const __half2*)&A[(size_t)(m0 + r) * Kd + k0 + c4];
        float2 f0 = __half22float2(ap[0]);
        float2 f1 = __half22float2(ap[1]);
        As[r][c4+0] = f0.x; As[r][c4+1] = f0.y; As[r][c4+2] = f1.x; As[r][c4+3] = f1.y;
        int r2 = tid >> 3, c8 = (tid & 7) * 8;
        float4 w0 = *(const float4*)&W1[(size_t)r2 * Kd + k0 + c8];
        float4 w1 = *(const float4*)&W1[(size_t)r2 * Kd + k0 + c8 + 4];
        Ws[0][r2][c8+0]=w0.x; Ws[0][r2][c8+1]=w0.y; Ws[0][r2][c8+2]=w0.z; Ws[0][r2][c8+3]=w0.w;
        Ws[0][r2][c8+4]=w1.x; Ws[0][r2][c8+5]=w1.y; Ws[0][r2][c8+6]=w1.z; Ws[0][r2][c8+7]=w1.w;
        float4 x0 = *(const float4*)&W2[(size_t)r2 * Kd + k0 + c8];
        float4 x1 = *(const float4*)&W2[(size_t)r2 * Kd + k0 + c8 + 4];
        Ws[1][r2][c8+0]=x0.x; Ws[1][r2][c8+1]=x0.y; Ws[1][r2][c8+2]=x0.z; Ws[1][r2][c8+3]=x0.w;
        Ws[1][r2][c8+4]=x1.x; Ws[1][r2][c8+5]=x1.y; Ws[1][r2][c8+6]=x1.z; Ws[1][r2][c8+7]=x1.w;
        __syncthreads();
        #pragma unroll
        for (int kk = 0; kk < 64; kk++) {
            float a0 = As[ty][kk], a1 = As[ty + 8][kk];
            float wv1 = Ws[0][tx][kk], wv2 = Ws[1][tx][kk];
            u0 += a0 * wv1;  u1 += a1 * wv1;
            t0a += a0 * wv2; t1a += a1 * wv2;
        }
        __syncthreads();
    }
    U[(size_t)(m0 + ty) * Kk + tx]     = u0;
    U[(size_t)(m0 + ty + 8) * Kk + tx] = u1;
    float bb = b2[tx];
    TG[(size_t)(m0 + ty) * Kk + tx]     = 1.f / (1.f + __expf(-(t0a + bb)));
    TG[(size_t)(m0 + ty + 8) * Kk + tx] = 1.f / (1.f + __expf(-(t1a + bb)));
}

// ---------------- chunked parallel oscillator scan ----------------
__global__ void scan_kernel(const float* __restrict__ u, const float* __restrict__ a_logit,
                            const float* __restrict__ theta, float* __restrict__ y) {
    __shared__ float ssr[32][33], ssi[32][33];
    int b = blockIdx.x;
    int tid = threadIdx.x;
    int k = tid & 31, c = tid >> 5;
    float a  = 1.f / (1.f + __expf(-a_logit[k]));
    float ct = cosf(theta[k]), st = sinf(theta[k]);
    const float* up = u + (size_t)b * Tt * Kk + k;
    int t0 = c * 64;

    float sr = 0.f, si = 0.f;
    for (int i = 0; i < 64; i++) {
        float ut = up[(size_t)(t0 + i) * Kk];
        float nsr = a * (ct * sr - st * si) + ut;
        float nsi = a * (st * sr + ct * si);
        sr = nsr; si = nsi;
    }
    ssr[c][k] = sr; ssi[c][k] = si;
    __syncthreads();

    if (tid < 32) {
        int kq = tid;
        float aq = 1.f / (1.f + __expf(-a_logit[kq]));
        float a64 = __powf(aq, 64.f);
        float th = theta[kq];
        float c64 = cosf(64.f * th), s64 = sinf(64.f * th);
        float M00 = a64 * c64, M01 = -a64 * s64;
        float M10 = a64 * s64, M11 =  a64 * c64;
        float cr = 0.f, ci = 0.f;
        for (int cc = 0; cc < 32; cc++) {
            float lr = ssr[cc][kq], li = ssi[cc][kq];
            ssr[cc][kq] = cr; ssi[cc][kq] = ci;
            float nr = M00 * cr + M01 * ci + lr;
            float ni = M10 * cr + M11 * ci + li;
            cr = nr; ci = ni;
        }
    }
    __syncthreads();

    sr = ssr[c][k]; si = ssi[c][k];
    float* yp = y + (size_t)b * Tt * Kk + k;
    for (int i = 0; i < 64; i++) {
        float ut = up[(size_t)(t0 + i) * Kk];
        float nsr = a * (ct * sr - st * si) + ut;
        float nsi = a * (st * sr + ct * si);
        sr = nsr; si = nsi;
        yp[(size_t)(t0 + i) * Kk] = sr;
    }
}

// ---------------- trn_out ----------------
__global__ void trn_out_kernel(const float* __restrict__ tg, const float* __restrict__ y,
                               const float* __restrict__ wout, const float* __restrict__ scale_p,
                               float* __restrict__ out) {
    __shared__ float Zs[16][33];
    __shared__ float Ws[64][33];
    int tx = threadIdx.x, ty = threadIdx.y;
    int tid = ty * 64 + tx;
    int m0 = blockIdx.x * 16, c0 = blockIdx.y * 64;
    for (int i = tid; i < 16 * Kk; i += 256) {
        int r = i >> 5, k = i & 31;
        size_t off = (size_t)(m0 + r) * Kk + k;
        Zs[r][k] = tg[off] * y[off];
    }
    for (int i = tid; i < 64 * Kk; i += 256) {
        int r = i >> 5, k = i & 31;
        Ws[r][k] = wout[(size_t)(c0 + r) * Kk + k];
    }
    __syncthreads();
    float scale = scale_p[0];
    float acc[4] = {0.f, 0.f, 0.f, 0.f};
    #pragma unroll
    for (int k = 0; k < Kk; k++) {
        float wv = Ws[tx][k];
        acc[0] += Zs[ty][k]      * wv;
        acc[1] += Zs[ty + 4][k]  * wv;
        acc[2] += Zs[ty + 8][k]  * wv;
        acc[3] += Zs[ty + 12][k] * wv;
    }
    #pragma unroll
    for (int r = 0; r < 4; r++)
        out[(size_t)(m0 + ty + 4 * r) * Cc + c0 + tx] = acc[r] * scale;
}

// ---------------- launch ----------------
extern "C" void kernel_launch(void* const* d_in, const int* in_sizes, int n_in,
                              void* d_out, int out_size) {
    const float* x          = (const float*)d_in[0];
    const float* norm1_w    = (const float*)d_in[1];
    const float* qkv_w      = (const float*)d_in[2];
    const float* qkv_b      = (const float*)d_in[3];
    const float* proj_w     = (const float*)d_in[4];
    const float* proj_b     = (const float*)d_in[5];
    const float* gate_w     = (const float*)d_in[6];
    const float* gate_b     = (const float*)d_in[7];
    const float* trn_win    = (const float*)d_in[8];
    const float* trn_wout   = (const float*)d_in[9];
    const float* trn_gate_w = (const float*)d_in[10];
    const float* trn_gate_b = (const float*)d_in[11];
    const float* trn_a      = (const float*)d_in[12];
    const float* trn_theta  = (const float*)d_in[13];
    const float* trn_scale  = (const float*)d_in[14];
    const float* norm2_w    = (const float*)d_in[15];
    const float* ffn_gate_w = (const float*)d_in[16];
    const float* ffn_up_w   = (const float*)d_in[17];
    const float* ffn_down_w = (const float*)d_in[18];
    float* out = (float*)d_out;

    __half *h, *qkv, *ao, *f1h, *wq, *wp, *wg, *wu, *wd;
    float *proj, *u, *y, *tg, *trn, *gate, *x1, *f1;
    cudaGetSymbolAddress((void**)&h,    g_h);
    cudaGetSymbolAddress((void**)&qkv,  g_qkv);
    cudaGetSymbolAddress((void**)&ao,   g_ao);
    cudaGetSymbolAddress((void**)&proj, g_proj);
    cudaGetSymbolAddress((void**)&u,    g_u);
    cudaGetSymbolAddress((void**)&y,    g_y);
    cudaGetSymbolAddress((void**)&tg,   g_tg);
    cudaGetSymbolAddress((void**)&trn,  g_trn);
    cudaGetSymbolAddress((void**)&gate, g_gate);
    cudaGetSymbolAddress((void**)&x1,   g_x1);
    cudaGetSymbolAddress((void**)&f1,   g_f1);
    cudaGetSymbolAddress((void**)&f1h,  g_f1h);
    cudaGetSymbolAddress((void**)&wq,   g_wq);
    cudaGetSymbolAddress((void**)&wp,   g_wp);
    cudaGetSymbolAddress((void**)&wg,   g_wg);
    cudaGetSymbolAddress((void**)&wu,   g_wu);
    cudaGetSymbolAddress((void**)&wd,   g_wd);

    cudaFuncSetAttribute(attn_mma, cudaFuncAttributeMaxDynamicSharedMemorySize, ATTN_SMEM);
    cudaFuncSetAttribute(hgemm<0>, cudaFuncAttributeMaxDynamicSharedMemorySize, HG_SMEM);
    cudaFuncSetAttribute(hgemm<1>, cudaFuncAttributeMaxDynamicSharedMemorySize, HG_SMEM);
    cudaFuncSetAttribute(hgemm<2>, cudaFuncAttributeMaxDynamicSharedMemorySize, HG_SMEM);
    cudaFuncSetAttribute(hgemm<3>, cudaFuncAttributeMaxDynamicSharedMemorySize, HG_SMEM);
    cudaFuncSetAttribute(hgemm<4>, cudaFuncAttributeMaxDynamicSharedMemorySize, HG_SMEM);

    // 0) pre-convert all weights to half (single launch)
    round_all_kernel<<<(R_TOT + 255) / 256, 256>>>(qkv_w, wq, proj_w, wp,
                                                   ffn_gate_w, wg, ffn_up_w, wu,
                                                   ffn_down_w, wd);

    // 1) h = rms(x, norm1_w) [half] + gate scalar (fused)
    rms_gate_kernel<<<Mrows, 256>>>(x, norm1_w, gate_w, gate_b, h, gate);
    // 2) qkv = h @ qkv_w^T + qkv_b [half out]
    hgemm<4><<<dim3(3 * Cc / TBN, Mrows / TBM), 256, HG_SMEM>>>(h, wq, qkv_b, nullptr, qkv, Mrows, 3 * Cc, Cc);
    // 3) attention (MMA, half scores, 3 CTAs/SM)
    attn_mma<<<dim3(Tt / QT, Hh, Bb), 256, ATTN_SMEM>>>(qkv, ao);
    // 4) proj [float out]
    hgemm<1><<<dim3(Cc / TBN, Mrows / TBM), 256, HG_SMEM>>>(ao, wp, proj_b, nullptr, proj, Mrows, Cc, Cc);
    // 5) TRN branch
    gemm_skinny2<<<Mrows / 16, dim3(32, 8)>>>(h, trn_win, trn_gate_w, trn_gate_b, u, tg, Cc);
    scan_kernel<<<Bb, 1024>>>(u, trn_a, trn_theta, y);
    trn_out_kernel<<<dim3(Mrows / 16, Cc / 64), dim3(64, 4)>>>(tg, y, trn_wout, trn_scale, trn);
    // 6) fused mix+rms2
    mix_rms_kernel<<<Mrows, 256>>>(x, proj, trn, gate, norm2_w, x1, h);
    // 7) FFN (f1 float)
    hgemm<0><<<dim3(DFFf / TBN, Mrows / TBM), 256, HG_SMEM>>>(h, wg, nullptr, nullptr, f1, Mrows, DFFf, Cc);
    hgemm<3><<<dim3(DFFf / TBN, Mrows / TBM), 256, HG_SMEM>>>(h, wu, nullptr, f1, f1h, Mrows, DFFf, Cc);
    // 8) out = f1h @ Wd^T + x1
    hgemm<2><<<dim3(Cc / TBN, Mrows / TBM), 256, HG_SMEM>>>(f1h, wd, nullptr, x1, out, Mrows, Cc, DFFf);
}

// round 17
// speedup vs baseline: 1.2361x; 1.1338x over previous
#include <cuda_runtime.h>
#include <cuda_fp16.h>
#include <math.h>
#include <stdint.h>

#define Bb   2
#define Tt   2048
#define Cc   1024
#define Hh   16
#define DHd  64
#define WINw 256
#define Kk   32
#define DFFf 4096
#define Mrows (Bb*Tt)   // 4096

// ---------------- scratch ----------------
__device__ __half g_h  [Mrows*Cc];
__device__ __half g_qkv[Mrows*3*Cc];
__device__ __half g_ao [Mrows*Cc];
__device__ float g_proj[Mrows*Cc];
__device__ float g_u   [Mrows*Kk];
__device__ float g_y   [Mrows*Kk];
__device__ float g_tg  [Mrows*Kk];
__device__ float g_trn [Mrows*Cc];
__device__ float g_gate[Mrows];
__device__ float g_x1  [Mrows*Cc];
__device__ float g_f1  [(size_t)Mrows*DFFf];
__device__ __half g_f1h[(size_t)Mrows*DFFf];
// half weight copies
__device__ __half g_wq [3*Cc*Cc];
__device__ __half g_wp [Cc*Cc];
__device__ __half g_wg [(size_t)DFFf*Cc];
__device__ __half g_wu [(size_t)DFFf*Cc];
__device__ __half g_wd [(size_t)Cc*DFFf];

// ---------------- common PTX helpers ----------------
__device__ __forceinline__ void cp_async16(unsigned sa, const void* gp) {
    asm volatile("cp.async.cg.shared.global [%0], [%1], 16;" :: "r"(sa), "l"(gp));
}
__device__ __forceinline__ void cp_async16z(unsigned sa, const void* gp, unsigned srcsz) {
    asm volatile("cp.async.cg.shared.global [%0], [%1], 16, %2;"
                 :: "r"(sa), "l"(gp), "r"(srcsz));
}
__device__ __forceinline__ void cp_commit() {
    asm volatile("cp.async.commit_group;");
}
template<int N>
__device__ __forceinline__ void cp_wait() {
    asm volatile("cp.async.wait_group %0;" :: "n"(N));
}
__device__ __forceinline__ void mma_f16(float* d, const unsigned* a, const unsigned* b) {
    asm volatile(
        "mma.sync.aligned.m16n8k16.row.col.f32.f16.f16.f32 "
        "{%0,%1,%2,%3}, {%4,%5,%6,%7}, {%8,%9}, {%0,%1,%2,%3};"
        : "+f"(d[0]), "+f"(d[1]), "+f"(d[2]), "+f"(d[3])
        : "r"(a[0]), "r"(a[1]), "r"(a[2]), "r"(a[3]), "r"(b[0]), "r"(b[1]));
}
__device__ __forceinline__ void ldsm_x4(unsigned& r0, unsigned& r1, unsigned& r2, unsigned& r3,
                                        unsigned addr) {
    asm volatile("ldmatrix.sync.aligned.m8n8.x4.shared.b16 {%0,%1,%2,%3}, [%4];"
                 : "=r"(r0), "=r"(r1), "=r"(r2), "=r"(r3) : "r"(addr));
}
__device__ __forceinline__ void ldsm_x4_t(unsigned& r0, unsigned& r1, unsigned& r2, unsigned& r3,
                                          unsigned addr) {
    asm volatile("ldmatrix.sync.aligned.m8n8.x4.trans.shared.b16 {%0,%1,%2,%3}, [%4];"
                 : "=r"(r0), "=r"(r1), "=r"(r2), "=r"(r3) : "r"(addr));
}

// ---------------- merged weight half pre-round (one launch for all 5) ----------------
#define RQ_N (3*Cc*Cc/4)
#define RP_N (Cc*Cc/4)
#define RF_N (DFFf*Cc/4)
#define R_TOT (RQ_N + RP_N + 3*RF_N)
__global__ void round_all_kernel(const float* __restrict__ qw, __half* __restrict__ dq,
                                 const float* __restrict__ pw, __half* __restrict__ dp,
                                 const float* __restrict__ gw, __half* __restrict__ dg,
                                 const float* __restrict__ uw, __half* __restrict__ du,
                                 const float* __restrict__ dw, __half* __restrict__ dd) {
    int idx = blockIdx.x * blockDim.x + threadIdx.x;
    if (idx >= R_TOT) return;
    const float* in; __half* out; int base;
    if (idx < RQ_N)                       { in = qw; out = dq; base = 0; }
    else if (idx < RQ_N + RP_N)           { in = pw; out = dp; base = RQ_N; }
    else if (idx < RQ_N + RP_N + RF_N)    { in = gw; out = dg; base = RQ_N + RP_N; }
    else if (idx < RQ_N + RP_N + 2*RF_N)  { in = uw; out = du; base = RQ_N + RP_N + RF_N; }
    else                                  { in = dw; out = dd; base = RQ_N + RP_N + 2*RF_N; }
    int i = idx - base;
    float4 v = ((const float4*)in)[i];
    __half2 a = __floats2half2_rn(v.x, v.y);
    __half2 b = __floats2half2_rn(v.z, v.w);
    ((uint2*)out)[i] = make_uint2(*(unsigned*)&a, *(unsigned*)&b);
}

// ---------------- fused RMSNorm + scalar gate ----------------
__global__ void rms_gate_kernel(const float* __restrict__ x, const float* __restrict__ w,
                                const float* __restrict__ gw, const float* __restrict__ gb,
                                __half* __restrict__ o, float* __restrict__ g) {
    int row = blockIdx.x;
    int tid = threadIdx.x;
    const float4* xr = (const float4*)(x + (size_t)row * Cc);
    float4 v = xr[tid];
    float s = v.x*v.x + v.y*v.y + v.z*v.z + v.w*v.w;
    __shared__ float red[8];
    int lane = tid & 31, warp = tid >> 5;
    #pragma unroll
    for (int o2 = 16; o2; o2 >>= 1) s += __shfl_xor_sync(0xffffffffu, s, o2);
    if (lane == 0) red[warp] = s;
    __syncthreads();
    if (warp == 0) {
        float t = (lane < 8) ? red[lane] : 0.f;
        #pragma unroll
        for (int o2 = 4; o2; o2 >>= 1) t += __shfl_xor_sync(0xffffffffu, t, o2);
        if (lane == 0) red[0] = t;
    }
    __syncthreads();
    float inv = rsqrtf(red[0] * (1.0f / Cc) + 1e-6f);
    float4 wv = ((const float4*)w)[tid];
    float h0 = v.x*inv*wv.x, h1 = v.y*inv*wv.y, h2 = v.z*inv*wv.z, h3 = v.w*inv*wv.w;
    __half2* op = (__half2*)(o + (size_t)row * Cc + tid * 4);
    op[0] = __floats2half2_rn(h0, h1);
    op[1] = __floats2half2_rn(h2, h3);
    float4 gv = ((const float4*)gw)[tid];
    float sg = h0*gv.x + h1*gv.y + h2*gv.z + h3*gv.w;
    __syncthreads();
    #pragma unroll
    for (int o2 = 16; o2; o2 >>= 1) sg += __shfl_xor_sync(0xffffffffu, sg, o2);
    if (lane == 0) red[warp] = sg;
    __syncthreads();
    if (tid == 0) {
        float t = 0.f;
        #pragma unroll
        for (int i = 0; i < 8; i++) t += red[i];
        g[row] = 1.f / (1.f + __expf(-(t + gb[0])));
    }
}

// ---------------- fused mix + RMSNorm (x1 float, h half) ----------------
__global__ void mix_rms_kernel(const float* __restrict__ x, const float* __restrict__ ap,
                               const float* __restrict__ trn, const float* __restrict__ g,
                               const float* __restrict__ w,
                               float* __restrict__ x1, __half* __restrict__ h) {
    int row = blockIdx.x;
    int tid = threadIdx.x;
    size_t off = (size_t)row * Cc / 4 + tid;
    float gg = g[row];
    float og = 1.f - gg;
    float4 xv = ((const float4*)x)[off];
    float4 av = ((const float4*)ap)[off];
    float4 tv = ((const float4*)trn)[off];
    float4 v = make_float4(xv.x + gg*av.x + og*tv.x,
                           xv.y + gg*av.y + og*tv.y,
                           xv.z + gg*av.z + og*tv.z,
                           xv.w + gg*av.w + og*tv.w);
    ((float4*)x1)[off] = v;
    float s = v.x*v.x + v.y*v.y + v.z*v.z + v.w*v.w;
    __shared__ float red[8];
    int lane = tid & 31, warp = tid >> 5;
    #pragma unroll
    for (int o2 = 16; o2; o2 >>= 1) s += __shfl_xor_sync(0xffffffffu, s, o2);
    if (lane == 0) red[warp] = s;
    __syncthreads();
    if (warp == 0) {
        float t = (lane < 8) ? red[lane] : 0.f;
        #pragma unroll
        for (int o2 = 4; o2; o2 >>= 1) t += __shfl_xor_sync(0xffffffffu, t, o2);
        if (lane == 0) red[0] = t;
    }
    __syncthreads();
    float inv = rsqrtf(red[0] * (1.0f / Cc) + 1e-6f);
    float4 wv = ((const float4*)w)[tid];
    __half2* op = (__half2*)(h + (size_t)row * Cc + tid * 4);
    op[0] = __floats2half2_rn(v.x*inv*wv.x, v.y*inv*wv.y);
    op[1] = __floats2half2_rn(v.z*inv*wv.z, v.w*inv*wv.w);
}

// ---------------- FP16 GEMM: CTA 128x128, warp 32x64, TBK=32, 3-stage (R14 proven) ----------------
#define TBM 128
#define TBN 128
#define TBK 32
#define TLDKH 40
#define HG_BUFB (128*TLDKH*2)
#define HG_SMEM (3 * HG_BUFB * 2)      // 61440

// EPI: 0 none->f32, 1 +bias->f32, 2 +res(f32)->f32, 3 silu(res f32)*acc->half, 4 +bias->half
template<int EPI>
__global__ void __launch_bounds__(256, 2)
hgemm(const __half* __restrict__ A, const __half* __restrict__ W,
      const float* __restrict__ bias, const float* __restrict__ res,
      void* __restrict__ Cv, int M, int N, int Kd) {
    extern __shared__ __half hsm[];
    __half* Abase = hsm;
    __half* Wbase = hsm + 3 * 128 * TLDKH;
    int tid = threadIdx.x;
    int lane = tid & 31, wid = tid >> 5;
    int g = lane >> 2, t = lane & 3;
    int l8 = lane & 7, sel = lane >> 3;
    int wm = wid & 3, wn = wid >> 2;
    int bm = blockIdx.y, bn = blockIdx.x;
    const __half* Ap = A + (size_t)(bm * TBM) * Kd;
    const __half* Wp = W + (size_t)(bn * TBN) * Kd;
    int lr = tid >> 1;
    int cu0 = (tid & 1) * 2;

    unsigned a_st = (unsigned)__cvta_generic_to_shared(&Abase[lr*TLDKH + cu0*8]);
    unsigned w_st = (unsigned)__cvta_generic_to_shared(&Wbase[lr*TLDKH + cu0*8]);
    unsigned a_la[2], w_la[4];
    #pragma unroll
    for (int mi = 0; mi < 2; mi++)
        a_la[mi] = (unsigned)__cvta_generic_to_shared(
            &Abase[(wm*32 + mi*16 + (sel&1)*8 + l8)*TLDKH + (sel>>1)*8]);
    #pragma unroll
    for (int p = 0; p < 4; p++)
        w_la[p] = (unsigned)__cvta_generic_to_shared(
            &Wbase[(wn*64 + p*16 + (sel>>1)*8 + l8)*TLDKH + (sel&1)*8]);

    int niter = Kd / TBK;
    #pragma unroll
    for (int s = 0; s < 2; s++) {
        const __half* ga = Ap + (size_t)lr * Kd + s*TBK + cu0 * 8;
        const __half* gw = Wp + (size_t)lr * Kd + s*TBK + cu0 * 8;
        cp_async16(a_st + s*HG_BUFB, ga);      cp_async16(a_st + s*HG_BUFB + 16, ga + 8);
        cp_async16(w_st + s*HG_BUFB, gw);      cp_async16(w_st + s*HG_BUFB + 16, gw + 8);
        cp_commit();
    }

    float acc[2][8][4];
    #pragma unroll
    for (int mi = 0; mi < 2; mi++)
        #pragma unroll
        for (int ni = 0; ni < 8; ni++)
            #pragma unroll
            for (int j = 0; j < 4; j++) acc[mi][ni][j] = 0.f;

    unsigned co = 0;
    for (int it = 0; it < niter; it++) {
        if (it + 1 < niter) cp_wait<1>(); else cp_wait<0>();
        __syncthreads();
        #pragma unroll
        for (int ks = 0; ks < 2; ks++) {
            unsigned koff = co + ks * 32;
            unsigned afr[2][4];
            #pragma unroll
            for (int mi = 0; mi < 2; mi++)
                ldsm_x4(afr[mi][0], afr[mi][1], afr[mi][2], afr[mi][3], a_la[mi] + koff);
            unsigned bfr[8][2];
            #pragma unroll
            for (int p = 0; p < 4; p++)
                ldsm_x4(bfr[2*p][0], bfr[2*p][1], bfr[2*p+1][0], bfr[2*p+1][1], w_la[p] + koff);
            #pragma unroll
            for (int mi = 0; mi < 2; mi++)
                #pragma unroll
                for (int ni = 0; ni < 8; ni++)
                    mma_f16(acc[mi][ni], afr[mi], bfr[ni]);
        }
        if (it + 2 < niter) {
            unsigned so = co + 2*HG_BUFB; if (so >= 3*HG_BUFB) so -= 3*HG_BUFB;
            int k0 = (it + 2) * TBK;
            const __half* ga = Ap + (size_t)lr * Kd + k0 + cu0 * 8;
            const __half* gw = Wp + (size_t)lr * Kd + k0 + cu0 * 8;
            cp_async16(a_st + so, ga);      cp_async16(a_st + so + 16, ga + 8);
            cp_async16(w_st + so, gw);      cp_async16(w_st + so + 16, gw + 8);
            cp_commit();
        }
        co += HG_BUFB; if (co == 3*HG_BUFB) co = 0;
    }

    float* C = (float*)Cv;
    __half* Ch = (__half*)Cv;
    #pragma unroll
    for (int mi = 0; mi < 2; mi++) {
        #pragma unroll
        for (int ni = 0; ni < 8; ni++) {
            int row = bm*TBM + wm*32 + mi*16 + g;
            int col = bn*TBN + wn*64 + ni*8 + 2*t;
            float v0 = acc[mi][ni][0], v1 = acc[mi][ni][1];
            float v2 = acc[mi][ni][2], v3 = acc[mi][ni][3];
            if (EPI == 1 || EPI == 4) {
                float b0 = bias[col], b1 = bias[col + 1];
                v0 += b0; v1 += b1; v2 += b0; v3 += b1;
            }
            if (EPI == 2) {
                const float* r0 = res + (size_t)row * N + col;
                const float* r1 = res + (size_t)(row + 8) * N + col;
                v0 += r0[0]; v1 += r0[1]; v2 += r1[0]; v3 += r1[1];
            }
            if (EPI == 3) {
                const float* r0 = res + (size_t)row * N + col;
                const float* r1 = res + (size_t)(row + 8) * N + col;
                float s0 = r0[0], s1 = r0[1], s2 = r1[0], s3 = r1[1];
                v0 = s0 / (1.f + __expf(-s0)) * v0;
                v1 = s1 / (1.f + __expf(-s1)) * v1;
                v2 = s2 / (1.f + __expf(-s2)) * v2;
                v3 = s3 / (1.f + __expf(-s3)) * v3;
            }
            if (EPI == 3 || EPI == 4) {
                *(__half2*)&Ch[(size_t)row * N + col]       = __floats2half2_rn(v0, v1);
                *(__half2*)&Ch[(size_t)(row + 8) * N + col] = __floats2half2_rn(v2, v3);
            } else {
                *(float2*)&C[(size_t)row * N + col]       = make_float2(v0, v1);
                *(float2*)&C[(size_t)(row + 8) * N + col] = make_float2(v2, v3);
            }
        }
    }
}

// ---------------- MMA windowed attention (half scores; cp.async fills; 3 CTAs/SM) ----------------
#define QT 64
#define NJ 384
#define PHL 392
#define AT_QH   0
#define AT_KV   9216
#define AT_PH   18432
#define ATTN_SMEM (18432 + 64*PHL*2)   // 68608

__global__ void __launch_bounds__(256)
attn_mma(const __half* __restrict__ qkv, __half* __restrict__ ao) {
    extern __shared__ char smraw[];
    __half* Qh  = (__half*)(smraw + AT_QH);
    __half* KVh = (__half*)(smraw + AT_KV);
    __half* Ph  = (__half*)(smraw + AT_PH);

    int q0 = blockIdx.x * QT;
    int h = blockIdx.y, b = blockIdx.z;
    int tid = threadIdx.x;
    int lane = tid & 31, wid = tid >> 5;
    int wm = wid & 3, wn = wid >> 2;
    int l8 = lane & 7, sel = lane >> 3;
    int g = lane >> 2, t = lane & 3;
    const size_t rs = 3 * Cc;
    const __half* qbase = qkv + (size_t)b * Tt * rs + h * DHd;
    int kbase = q0 - 256;

    // per-thread fill coordinates (2 items each: i = tid, tid+256)
    unsigned kv_st[2];
    int fr[2], fc8[2];
    #pragma unroll
    for (int it = 0; it < 2; it++) {
        int i = tid + it*256;
        fr[it] = i >> 3; fc8[it] = (i & 7) * 8;
        kv_st[it] = (unsigned)__cvta_generic_to_shared(&KVh[fr[it]*72 + fc8[it]]);
    }

    // load Q via cp.async (always valid)
    #pragma unroll
    for (int it = 0; it < 2; it++) {
        unsigned q_st = (unsigned)__cvta_generic_to_shared(&Qh[fr[it]*72 + fc8[it]]);
        cp_async16(q_st, qbase + (size_t)(q0 + fr[it]) * rs + fc8[it]);
    }
    cp_commit();

    unsigned q_la = (unsigned)__cvta_generic_to_shared(
        &Qh[(wm*16 + (sel&1)*8 + l8)*72 + (sel>>1)*8]);
    unsigned k_la[2];
    #pragma unroll
    for (int p = 0; p < 2; p++)
        k_la[p] = (unsigned)__cvta_generic_to_shared(
            &KVh[(wn*32 + p*16 + (sel>>1)*8 + l8)*72 + (sel&1)*8]);
    unsigned v_la[2];
    #pragma unroll
    for (int p = 0; p < 2; p++)
        v_la[p] = (unsigned)__cvta_generic_to_shared(
            &KVh[((sel&1)*8 + l8)*72 + wn*32 + p*16 + (sel>>1)*8]);
    unsigned ph_la = (unsigned)__cvta_generic_to_shared(
        &Ph[(wm*16 + (sel&1)*8 + l8)*PHL + (sel>>1)*8]);

    // ---- phase 1: scores (half; masked = -60000) ----
    for (int cc = 0; cc < 6; cc++) {
        #pragma unroll
        for (int it = 0; it < 2; it++) {
            int kg = kbase + cc*64 + fr[it];
            bool ok = (kg >= 0 && kg < Tt);
            int kgc = ok ? kg : 0;
            cp_async16z(kv_st[it], qbase + Cc + (size_t)kgc * rs + fc8[it], ok ? 16u : 0u);
        }
        cp_commit();
        cp_wait<0>();
        __syncthreads();
        float acc[4][4] = {};
        #pragma unroll
        for (int ks = 0; ks < 4; ks++) {
            unsigned koff = ks * 32;
            unsigned af[4];
            ldsm_x4(af[0], af[1], af[2], af[3], q_la + koff);
            unsigned bf[4][2];
            #pragma unroll
            for (int p = 0; p < 2; p++)
                ldsm_x4(bf[2*p][0], bf[2*p][1], bf[2*p+1][0], bf[2*p+1][1], k_la[p] + koff);
            #pragma unroll
            for (int ni = 0; ni < 4; ni++)
                mma_f16(acc[ni], af, bf[ni]);
        }
        #pragma unroll
        for (int ni = 0; ni < 4; ni++) {
            int col = wn*32 + ni*8 + 2*t;
            int j0 = cc*64 + col;
            #pragma unroll
            for (int hh = 0; hh < 2; hh++) {
                int qi = wm*16 + g + hh*8;
                float v0 = acc[ni][2*hh]   * 0.125f;
                float v1 = acc[ni][2*hh+1] * 0.125f;
                bool ok0 = (j0   >= qi + 1) && (j0   <= qi + 256) && (kbase + j0   >= 0);
                bool ok1 = (j0+1 >= qi + 1) && (j0+1 <= qi + 256) && (kbase + j0+1 >= 0);
                *(__half2*)&Ph[qi*PHL + j0] =
                    __floats2half2_rn(ok0 ? v0 : -60000.f, ok1 ? v1 : -60000.f);
            }
        }
        __syncthreads();
    }

    // ---- phase 2: softmax in fp32 regs ----
    for (int q = wid; q < 64; q += 8) {
        float rv[12];
        #pragma unroll
        for (int jj = 0; jj < 12; jj++)
            rv[jj] = __half2float(Ph[q*PHL + lane + jj*32]);
        float m = rv[0];
        #pragma unroll
        for (int jj = 1; jj < 12; jj++) m = fmaxf(m, rv[jj]);
        #pragma unroll
        for (int o2 = 16; o2; o2 >>= 1) m = fmaxf(m, __shfl_xor_sync(0xffffffffu, m, o2));
        float s = 0.f;
        #pragma unroll
        for (int jj = 0; jj < 12; jj++) {
            rv[jj] = __expf(rv[jj] - m);
            s += rv[jj];
        }
        #pragma unroll
        for (int o2 = 16; o2; o2 >>= 1) s += __shfl_xor_sync(0xffffffffu, s, o2);
        float inv = 1.0f / s;
        #pragma unroll
        for (int jj = 0; jj < 12; jj++)
            Ph[q*PHL + lane + jj*32] = __float2half(rv[jj] * inv);
    }
    __syncthreads();

    // ---- phase 3: AV via MMA ----
    float oacc[4][4] = {};
    for (int cc = 0; cc < 6; cc++) {
        #pragma unroll
        for (int it = 0; it < 2; it++) {
            int kg = kbase + cc*64 + fr[it];
            bool ok = (kg >= 0 && kg < Tt);
            int kgc = ok ? kg : 0;
            cp_async16z(kv_st[it], qbase + 2*Cc + (size_t)kgc * rs + fc8[it], ok ? 16u : 0u);
        }
        cp_commit();
        cp_wait<0>();
        __syncthreads();
        #pragma unroll
        for (int ks = 0; ks < 4; ks++) {
            unsigned af[4];
            ldsm_x4(af[0], af[1], af[2], af[3], ph_la + cc*128 + ks*32);
            unsigned bf[4][2];
            #pragma unroll
            for (int p = 0; p < 2; p++)
                ldsm_x4_t(bf[2*p][0], bf[2*p][1], bf[2*p+1][0], bf[2*p+1][1],
                          v_la[p] + ks * (16*72*2));
            #pragma unroll
            for (int ni = 0; ni < 4; ni++)
                mma_f16(oacc[ni], af, bf[ni]);
        }
        __syncthreads();
    }

    #pragma unroll
    for (int ni = 0; ni < 4; ni++) {
        int col = wn*32 + ni*8 + 2*t;
        #pragma unroll
        for (int hh = 0; hh < 2; hh++) {
            int q = wm*16 + g + hh*8;
            *(__half2*)&ao[(size_t)(b*Tt + q0 + q)*Cc + h*DHd + col] =
                __floats2half2_rn(oacc[ni][2*hh], oacc[ni][2*hh+1]);
        }
    }
}

// ---------------- merged skinny GEMM ----------------
__global__ void gemm_skinny2(const __half* __restrict__ A,
                             const float* __restrict__ W1, const float* __restrict__ W2,
                             const float* __restrict__ b2,
                             float* __restrict__ U, float* __restrict__ TG, int Kd) {
    __shared__ float As[16][64];
    __shared__ float Ws[2][32][65];
    int tx = threadIdx.x, ty = threadIdx.y;
    int tid = ty * 32 + tx;
    int m0 = blockIdx.x * 16;
    float u0 = 0.f, u1 = 0.f, t0a = 0.f, t1a = 0.f;
    for (int k0 = 0; k0 < Kd; k0 += 64) {
        int r = tid >> 4, c4 = (tid & 15) * 4;
        const __half2* ap = (const __half2*)&A[(size_t)(m0 + r) * Kd + k0 + c4];
        float2 f0 = __half22float2(ap[0]);
        float2 f1 = __half22float2(ap[1]);
        As[r][c4+0] = f0.x; As[r][c4+1] = f0.y; As[r][c4+2] = f1.x; As[r][c4+3] = f1.y;
        int r2 = tid >> 3, c8 = (tid & 7) * 8;
        float4 w0 = *(const float4*)&W1[(size_t)r2 * Kd + k0 + c8];
        float4 w1 = *(const float4*)&W1[(size_t)r2 * Kd + k0 + c8 + 4];
        Ws[0][r2][c8+0]=w0.x; Ws[0][r2][c8+1]=w0.y; Ws[0][r2][c8+2]=w0.z; Ws[0][r2][c8+3]=w0.w;
        Ws[0][r2][c8+4]=w1.x; Ws[0][r2][c8+5]=w1.y; Ws[0][r2][c8+6]=w1.z; Ws[0][r2][c8+7]=w1.w;
        float4 x0 = *(const float4*)&W2[(size_t)r2 * Kd + k0 + c8];
        float4 x1 = *(const float4*)&W2[(size_t)r2 * Kd + k0 + c8 + 4];
        Ws[1][r2][c8+0]=x0.x; Ws[1][r2][c8+1]=x0.y; Ws[1][r2][c8+2]=x0.z; Ws[1][r2][c8+3]=x0.w;
        Ws[1][r2][c8+4]=x1.x; Ws[1][r2][c8+5]=x1.y; Ws[1][r2][c8+6]=x1.z; Ws[1][r2][c8+7]=x1.w;
        __syncthreads();
        #pragma unroll
        for (int kk = 0; kk < 64; kk++) {
            float a0 = As[ty][kk], a1 = As[ty + 8][kk];
            float wv1 = Ws[0][tx][kk], wv2 = Ws[1][tx][kk];
            u0 += a0 * wv1;  u1 += a1 * wv1;
            t0a += a0 * wv2; t1a += a1 * wv2;
        }
        __syncthreads();
    }
    U[(size_t)(m0 + ty) * Kk + tx]     = u0;
    U[(size_t)(m0 + ty + 8) * Kk + tx] = u1;
    float bb = b2[tx];
    TG[(size_t)(m0 + ty) * Kk + tx]     = 1.f / (1.f + __expf(-(t0a + bb)));
    TG[(size_t)(m0 + ty + 8) * Kk + tx] = 1.f / (1.f + __expf(-(t1a + bb)));
}

// ---------------- chunked parallel oscillator scan ----------------
__global__ void scan_kernel(const float* __restrict__ u, const float* __restrict__ a_logit,
                            const float* __restrict__ theta, float* __restrict__ y) {
    __shared__ float ssr[32][33], ssi[32][33];
    int b = blockIdx.x;
    int tid = threadIdx.x;
    int k = tid & 31, c = tid >> 5;
    float a  = 1.f / (1.f + __expf(-a_logit[k]));
    float ct = cosf(theta[k]), st = sinf(theta[k]);
    const float* up = u + (size_t)b * Tt * Kk + k;
    int t0 = c * 64;

    float sr = 0.f, si = 0.f;
    for (int i = 0; i < 64; i++) {
        float ut = up[(size_t)(t0 + i) * Kk];
        float nsr = a * (ct * sr - st * si) + ut;
        float nsi = a * (st * sr + ct * si);
        sr = nsr; si = nsi;
    }
    ssr[c][k] = sr; ssi[c][k] = si;
    __syncthreads();

    if (tid < 32) {
        int kq = tid;
        float aq = 1.f / (1.f + __expf(-a_logit[kq]));
        float a64 = __powf(aq, 64.f);
        float th = theta[kq];
        float c64 = cosf(64.f * th), s64 = sinf(64.f * th);
        float M00 = a64 * c64, M01 = -a64 * s64;
        float M10 = a64 * s64, M11 =  a64 * c64;
        float cr = 0.f, ci = 0.f;
        for (int cc = 0; cc < 32; cc++) {
            float lr = ssr[cc][kq], li = ssi[cc][kq];
            ssr[cc][kq] = cr; ssi[cc][kq] = ci;
            float nr = M00 * cr + M01 * ci + lr;
            float ni = M10 * cr + M11 * ci + li;
            cr = nr; ci = ni;
        }
    }
    __syncthreads();

    sr = ssr[c][k]; si = ssi[c][k];
    float* yp = y + (size_t)b * Tt * Kk + k;
    for (int i = 0; i < 64; i++) {
        float ut = up[(size_t)(t0 + i) * Kk];
        float nsr = a * (ct * sr - st * si) + ut;
        float nsi = a * (st * sr + ct * si);
        sr = nsr; si = nsi;
        yp[(size_t)(t0 + i) * Kk] = sr;
    }
}

// ---------------- trn_out ----------------
__global__ void trn_out_kernel(const float* __restrict__ tg, const float* __restrict__ y,
                               const float* __restrict__ wout, const float* __restrict__ scale_p,
                               float* __restrict__ out) {
    __shared__ float Zs[16][33];
    __shared__ float Ws[64][33];
    int tx = threadIdx.x, ty = threadIdx.y;
    int tid = ty * 64 + tx;
    int m0 = blockIdx.x * 16, c0 = blockIdx.y * 64;
    for (int i = tid; i < 16 * Kk; i += 256) {
        int r = i >> 5, k = i & 31;
        size_t off = (size_t)(m0 + r) * Kk + k;
        Zs[r][k] = tg[off] * y[off];
    }
    for (int i = tid; i < 64 * Kk; i += 256) {
        int r = i >> 5, k = i & 31;
        Ws[r][k] = wout[(size_t)(c0 + r) * Kk + k];
    }
    __syncthreads();
    float scale = scale_p[0];
    float acc[4] = {0.f, 0.f, 0.f, 0.f};
    #pragma unroll
    for (int k = 0; k < Kk; k++) {
        float wv = Ws[tx][k];
        acc[0] += Zs[ty][k]      * wv;
        acc[1] += Zs[ty + 4][k]  * wv;
        acc[2] += Zs[ty + 8][k]  * wv;
        acc[3] += Zs[ty + 12][k] * wv;
    }
    #pragma unroll
    for (int r = 0; r < 4; r++)
        out[(size_t)(m0 + ty + 4 * r) * Cc + c0 + tx] = acc[r] * scale;
}

// ---------------- launch ----------------
extern "C" void kernel_launch(void* const* d_in, const int* in_sizes, int n_in,
                              void* d_out, int out_size) {
    const float* x          = (const float*)d_in[0];
    const float* norm1_w    = (const float*)d_in[1];
    const float* qkv_w      = (const float*)d_in[2];
    const float* qkv_b      = (const float*)d_in[3];
    const float* proj_w     = (const float*)d_in[4];
    const float* proj_b     = (const float*)d_in[5];
    const float* gate_w     = (const float*)d_in[6];
    const float* gate_b     = (const float*)d_in[7];
    const float* trn_win    = (const float*)d_in[8];
    const float* trn_wout   = (const float*)d_in[9];
    const float* trn_gate_w = (const float*)d_in[10];
    const float* trn_gate_b = (const float*)d_in[11];
    const float* trn_a      = (const float*)d_in[12];
    const float* trn_theta  = (const float*)d_in[13];
    const float* trn_scale  = (const float*)d_in[14];
    const float* norm2_w    = (const float*)d_in[15];
    const float* ffn_gate_w = (const float*)d_in[16];
    const float* ffn_up_w   = (const float*)d_in[17];
    const float* ffn_down_w = (const float*)d_in[18];
    float* out = (float*)d_out;

    __half *h, *qkv, *ao, *f1h, *wq, *wp, *wg, *wu, *wd;
    float *proj, *u, *y, *tg, *trn, *gate, *x1, *f1;
    cudaGetSymbolAddress((void**)&h,    g_h);
    cudaGetSymbolAddress((void**)&qkv,  g_qkv);
    cudaGetSymbolAddress((void**)&ao,   g_ao);
    cudaGetSymbolAddress((void**)&proj, g_proj);
    cudaGetSymbolAddress((void**)&u,    g_u);
    cudaGetSymbolAddress((void**)&y,    g_y);
    cudaGetSymbolAddress((void**)&tg,   g_tg);
    cudaGetSymbolAddress((void**)&trn,  g_trn);
    cudaGetSymbolAddress((void**)&gate, g_gate);
    cudaGetSymbolAddress((void**)&x1,   g_x1);
    cudaGetSymbolAddress((void**)&f1,   g_f1);
    cudaGetSymbolAddress((void**)&f1h,  g_f1h);
    cudaGetSymbolAddress((void**)&wq,   g_wq);
    cudaGetSymbolAddress((void**)&wp,   g_wp);
    cudaGetSymbolAddress((void**)&wg,   g_wg);
    cudaGetSymbolAddress((void**)&wu,   g_wu);
    cudaGetSymbolAddress((void**)&wd,   g_wd);

    cudaFuncSetAttribute(attn_mma, cudaFuncAttributeMaxDynamicSharedMemorySize, ATTN_SMEM);
    cudaFuncSetAttribute(hgemm<0>, cudaFuncAttributeMaxDynamicSharedMemorySize, HG_SMEM);
    cudaFuncSetAttribute(hgemm<1>, cudaFuncAttributeMaxDynamicSharedMemorySize, HG_SMEM);
    cudaFuncSetAttribute(hgemm<2>, cudaFuncAttributeMaxDynamicSharedMemorySize, HG_SMEM);
    cudaFuncSetAttribute(hgemm<3>, cudaFuncAttributeMaxDynamicSharedMemorySize, HG_SMEM);
    cudaFuncSetAttribute(hgemm<4>, cudaFuncAttributeMaxDynamicSharedMemorySize, HG_SMEM);

    // 0) pre-convert all weights to half (single launch)
    round_all_kernel<<<(R_TOT + 255) / 256, 256>>>(qkv_w, wq, proj_w, wp,
                                                   ffn_gate_w, wg, ffn_up_w, wu,
                                                   ffn_down_w, wd);

    // 1) h = rms(x, norm1_w) [half] + gate scalar (fused)
    rms_gate_kernel<<<Mrows, 256>>>(x, norm1_w, gate_w, gate_b, h, gate);
    // 2) qkv = h @ qkv_w^T + qkv_b [half out]
    hgemm<4><<<dim3(3 * Cc / TBN, Mrows / TBM), 256, HG_SMEM>>>(h, wq, qkv_b, nullptr, qkv, Mrows, 3 * Cc, Cc);
    // 3) attention (MMA, half scores, cp.async fills, 3 CTAs/SM)
    attn_mma<<<dim3(Tt / QT, Hh, Bb), 256, ATTN_SMEM>>>(qkv, ao);
    // 4) proj [float out]
    hgemm<1><<<dim3(Cc / TBN, Mrows / TBM), 256, HG_SMEM>>>(ao, wp, proj_b, nullptr, proj, Mrows, Cc, Cc);
    // 5) TRN branch
    gemm_skinny2<<<Mrows / 16, dim3(32, 8)>>>(h, trn_win, trn_gate_w, trn_gate_b, u, tg, Cc);
    scan_kernel<<<Bb, 1024>>>(u, trn_a, trn_theta, y);
    trn_out_kernel<<<dim3(Mrows / 16, Cc / 64), dim3(64, 4)>>>(tg, y, trn_wout, trn_scale, trn);
    // 6) fused mix+rms2
    mix_rms_kernel<<<Mrows, 256>>>(x, proj, trn, gate, norm2_w, x1, h);
    // 7) FFN (f1 float)
    hgemm<0><<<dim3(DFFf / TBN, Mrows / TBM), 256, HG_SMEM>>>(h, wg, nullptr, nullptr, f1, Mrows, DFFf, Cc);
    hgemm<3><<<dim3(DFFf / TBN, Mrows / TBM), 256, HG_SMEM>>>(h, wu, nullptr, f1, f1h, Mrows, DFFf, Cc);
    // 8) out = f1h @ Wd^T + x1
    hgemm<2><<<dim3(Cc / TBN, Mrows / TBM), 256, HG_SMEM>>>(f1h, wd, nullptr, x1, out, Mrows, Cc, DFFf);
}